// round 2
// baseline (speedup 1.0000x reference)
#include <cuda_runtime.h>
#include <cuda_bf16.h>
#include <math.h>

// Problem constants
#define BATCH 4
#define SEQ   1024
#define EMB   1024
#define HEADS 16
#define HDIM  64
#define HID   1024            // HEADS*HDIM
#define WIN   128             // half-window
#define NREL  257             // 2*WIN+1
#define NRELP 384             // padded to multiple of 128 for GEMM

// ---------------- scratch (no cudaMalloc allowed) ----------------
__device__ float g_qc[(size_t)BATCH*HEADS*SEQ*HDIM];   // q + content_bias, [b][h][t][d]
__device__ float g_qr[(size_t)BATCH*HEADS*SEQ*HDIM];   // q + relative_bias
__device__ float g_k [(size_t)BATCH*HEADS*SEQ*HDIM];
__device__ float g_v [(size_t)BATCH*HEADS*SEQ*HDIM];
__device__ float g_rel[(size_t)BATCH*HEADS*SEQ*NRELP]; // REL[b,h,t,u]
__device__ float g_ao[(size_t)BATCH*SEQ*HID];          // attention output, [b][t][h*64+d]
__device__ float g_rwint[64*NRELP];                    // RwinT[d][u]

// ---------------- Rwin precompute ----------------
// RwinT[d][u] = b_rel[d] + sum_dd enc(pos=u-128, dd) * W_rel[dd][d],  u in [0,257)
__global__ void rwin_kernel(const float* __restrict__ W_rel,
                            const float* __restrict__ b_rel,
                            float* __restrict__ RwinT) {
    int gid = blockIdx.x * blockDim.x + threadIdx.x;
    if (gid >= 64 * NRELP) return;
    int u = gid % NRELP;
    int d = gid / NRELP;
    float out = 0.0f;
    if (u < NREL) {
        float pos = (float)(u - WIN);
        float s = b_rel[d];
        #pragma unroll 8
        for (int f = 0; f < 32; f++) {
            float inv = powf(10000.0f, -(2.0f * (float)f) / 64.0f);
            float a = pos * inv;
            s += sinf(a) * W_rel[f * 64 + d];
            s += cosf(a) * W_rel[(f + 32) * 64 + d];
        }
        out = s;
    }
    RwinT[d * NRELP + u] = out;
}

// ---------------- generic fp32 SGEMM, 128x128x16, 256 threads, 8x8 microtile ----
// modes: 0 rowmajor C; 1 rowmajor C + bias1[n]; 2 bhtd layout C;
//        3 bhtd layout, C = acc + bias1[n], C2 = acc + bias2[n]
__global__ void __launch_bounds__(256, 2)
sgemm_kernel(const float* __restrict__ A, int lda,
             const float* __restrict__ B, int ldb,
             float* __restrict__ C, float* __restrict__ C2,
             const float* __restrict__ bias1,
             const float* __restrict__ bias2,
             int M, int N, int K, int mode) {
    __shared__ float As[16][132];
    __shared__ float Bs[16][132];

    int tid = threadIdx.x;
    int tx = tid & 15, ty = tid >> 4;
    int m0 = blockIdx.y * 128, n0 = blockIdx.x * 128;
    int arow = tid >> 2;            // 0..63
    int acol = (tid & 3) << 2;      // 0,4,8,12
    int brow = tid >> 5;            // 0..7
    int bcol = (tid & 31) << 2;     // 0..124

    float acc[8][8];
    #pragma unroll
    for (int i = 0; i < 8; i++)
        #pragma unroll
        for (int j = 0; j < 8; j++) acc[i][j] = 0.0f;

    for (int k0 = 0; k0 < K; k0 += 16) {
        #pragma unroll
        for (int r = 0; r < 128; r += 64) {
            float4 v = *(const float4*)(A + (size_t)(m0 + arow + r) * lda + k0 + acol);
            As[acol + 0][arow + r] = v.x;
            As[acol + 1][arow + r] = v.y;
            As[acol + 2][arow + r] = v.z;
            As[acol + 3][arow + r] = v.w;
        }
        #pragma unroll
        for (int r = 0; r < 16; r += 8) {
            float4 v = *(const float4*)(B + (size_t)(k0 + brow + r) * ldb + n0 + bcol);
            *(float4*)&Bs[brow + r][bcol] = v;
        }
        __syncthreads();
        #pragma unroll
        for (int kk = 0; kk < 16; kk++) {
            float4 a0 = *(float4*)&As[kk][ty * 8];
            float4 a1 = *(float4*)&As[kk][ty * 8 + 4];
            float4 b0 = *(float4*)&Bs[kk][tx * 8];
            float4 b1 = *(float4*)&Bs[kk][tx * 8 + 4];
            float av[8] = {a0.x, a0.y, a0.z, a0.w, a1.x, a1.y, a1.z, a1.w};
            float bv[8] = {b0.x, b0.y, b0.z, b0.w, b1.x, b1.y, b1.z, b1.w};
            #pragma unroll
            for (int i = 0; i < 8; i++)
                #pragma unroll
                for (int j = 0; j < 8; j++) acc[i][j] += av[i] * bv[j];
        }
        __syncthreads();
    }

    if (mode <= 1) {
        #pragma unroll
        for (int i = 0; i < 8; i++) {
            int m = m0 + ty * 8 + i;
            size_t off = (size_t)m * N + n0 + tx * 8;
            #pragma unroll
            for (int j = 0; j < 8; j++) {
                float v = acc[i][j];
                if (mode == 1) v += bias1[n0 + tx * 8 + j];
                C[off + j] = v;
            }
        }
    } else {
        #pragma unroll
        for (int i = 0; i < 8; i++) {
            int m = m0 + ty * 8 + i;
            int bb = m >> 10, t = m & 1023;
            #pragma unroll
            for (int j = 0; j < 8; j++) {
                int n = n0 + tx * 8 + j;
                int hh = n >> 6, dd = n & 63;
                size_t idx = ((size_t)(bb * HEADS + hh) << 16) + ((size_t)t << 6) + dd;
                if (mode == 2) {
                    C[idx] = acc[i][j];
                } else {
                    C[idx]  = acc[i][j] + bias1[n];
                    C2[idx] = acc[i][j] + bias2[n];
                }
            }
        }
    }
}

// ---------------- windowed attention ----------------
// block: (tile of 64 queries, h, b). 256 threads.
#define TQ   64
#define SPAN 320        // TQ + 2*WIN
#define SP   328        // padded Ssm row
#define DP   68         // padded 64-wide rows
#define ATTN_SMEM_FLOATS (2 * 64 * DP + 64 * SP)

__global__ void __launch_bounds__(256, 1)
attn_kernel(const float* __restrict__ QC,
            const float* __restrict__ KT,
            const float* __restrict__ VT,
            const float* __restrict__ REL,
            float* __restrict__ AO) {
    extern __shared__ float sm[];
    float* Qst = sm;                  // [64][DP]  Qst[d][t]
    float* Kst = sm + 64 * DP;        // [64][DP]  Kst[d][j]; reused as Vs[j][d]
    float* Ssm = sm + 2 * 64 * DP;    // [64][SP]

    int tid = threadIdx.x;
    int tx = tid & 15, ty = tid >> 4;
    int t0 = blockIdx.x * TQ;
    int h = blockIdx.y, b = blockIdx.z;
    size_t bh = (size_t)(b * HEADS + h);
    const float* qb = QC + (bh << 16) + (size_t)t0 * HDIM;
    const float* kb = KT + (bh << 16);
    const float* vb = VT + (bh << 16);
    const float* relb = REL + (bh * SEQ + t0) * NRELP;

    // load Q tile transposed: Qst[d][t]
    #pragma unroll
    for (int l = 0; l < 4; l++) {
        int fidx = tid + l * 256;          // 1024 float4s
        int t = fidx >> 4;
        int d = (fidx & 15) << 2;
        float4 v = *(const float4*)(qb + t * HDIM + d);
        Qst[(d + 0) * DP + t] = v.x;
        Qst[(d + 1) * DP + t] = v.y;
        Qst[(d + 2) * DP + t] = v.z;
        Qst[(d + 3) * DP + t] = v.w;
    }

    // ---- scores S = Qc @ K^T  (+ REL gather, scale, mask) ----
    for (int c = 0; c < 5; c++) {
        int j0 = t0 - WIN + c * 64;
        __syncthreads();   // Kst free (also orders Q load before first compute)
        #pragma unroll
        for (int l = 0; l < 4; l++) {
            int fidx = tid + l * 256;
            int jl = fidx >> 4;
            int d = (fidx & 15) << 2;
            int jg = j0 + jl;
            float4 v = make_float4(0.f, 0.f, 0.f, 0.f);
            if (jg >= 0 && jg < SEQ) v = *(const float4*)(kb + (size_t)jg * HDIM + d);
            Kst[(d + 0) * DP + jl] = v.x;
            Kst[(d + 1) * DP + jl] = v.y;
            Kst[(d + 2) * DP + jl] = v.z;
            Kst[(d + 3) * DP + jl] = v.w;
        }
        __syncthreads();

        float acc[4][4];
        #pragma unroll
        for (int i = 0; i < 4; i++)
            #pragma unroll
            for (int j = 0; j < 4; j++) acc[i][j] = 0.0f;

        #pragma unroll 8
        for (int kk = 0; kk < 64; kk++) {
            float4 a = *(float4*)&Qst[kk * DP + ty * 4];
            float4 bb = *(float4*)&Kst[kk * DP + tx * 4];
            float av[4] = {a.x, a.y, a.z, a.w};
            float bv[4] = {bb.x, bb.y, bb.z, bb.w};
            #pragma unroll
            for (int i = 0; i < 4; i++)
                #pragma unroll
                for (int j = 0; j < 4; j++) acc[i][j] += av[i] * bv[j];
        }

        #pragma unroll
        for (int i = 0; i < 4; i++) {
            int t = ty * 4 + i;
            int tq = t0 + t;
            #pragma unroll
            for (int j = 0; j < 4; j++) {
                int jl = tx * 4 + j;
                int jg = j0 + jl;
                int u = tq - jg + WIN;
                float val = -1e30f;
                if (jg >= 0 && jg < SEQ && u >= 0 && u < NREL)
                    val = (acc[i][j] + relb[(size_t)t * NRELP + u]) * 0.03125f;
                Ssm[t * SP + c * 64 + jl] = val;
            }
        }
    }
    __syncthreads();

    // ---- softmax per row (8 warps x 8 rows) ----
    {
        int w = tid >> 5, lane = tid & 31;
        for (int t = w * 8; t < w * 8 + 8; t++) {
            float* row = Ssm + t * SP;
            float m = -1e30f;
            for (int idx = lane; idx < SPAN; idx += 32) m = fmaxf(m, row[idx]);
            #pragma unroll
            for (int o = 16; o > 0; o >>= 1) m = fmaxf(m, __shfl_xor_sync(0xffffffffu, m, o));
            float s = 0.0f;
            for (int idx = lane; idx < SPAN; idx += 32) {
                float e = __expf(row[idx] - m);
                row[idx] = e;
                s += e;
            }
            #pragma unroll
            for (int o = 16; o > 0; o >>= 1) s += __shfl_xor_sync(0xffffffffu, s, o);
            float inv = 1.0f / s;
            for (int idx = lane; idx < SPAN; idx += 32) row[idx] *= inv;
        }
    }

    // ---- O = P @ V ----
    float acco[4][4];
    #pragma unroll
    for (int i = 0; i < 4; i++)
        #pragma unroll
        for (int j = 0; j < 4; j++) acco[i][j] = 0.0f;

    float* Vs = Kst;   // reuse
    for (int c = 0; c < 5; c++) {
        int j0 = t0 - WIN + c * 64;
        __syncthreads();   // Ssm reads from softmax done; Vs free
        #pragma unroll
        for (int l = 0; l < 4; l++) {
            int fidx = tid + l * 256;
            int jl = fidx >> 4;
            int d = (fidx & 15) << 2;
            int jg = j0 + jl;
            float4 v = make_float4(0.f, 0.f, 0.f, 0.f);
            if (jg >= 0 && jg < SEQ) v = *(const float4*)(vb + (size_t)jg * HDIM + d);
            *(float4*)&Vs[jl * DP + d] = v;
        }
        __syncthreads();

        #pragma unroll 8
        for (int jk = 0; jk < 64; jk++) {
            float a0 = Ssm[(ty * 4 + 0) * SP + c * 64 + jk];
            float a1 = Ssm[(ty * 4 + 1) * SP + c * 64 + jk];
            float a2 = Ssm[(ty * 4 + 2) * SP + c * 64 + jk];
            float a3 = Ssm[(ty * 4 + 3) * SP + c * 64 + jk];
            float4 bb = *(float4*)&Vs[jk * DP + tx * 4];
            float bv[4] = {bb.x, bb.y, bb.z, bb.w};
            float av[4] = {a0, a1, a2, a3};
            #pragma unroll
            for (int i = 0; i < 4; i++)
                #pragma unroll
                for (int j = 0; j < 4; j++) acco[i][j] += av[i] * bv[j];
        }
    }

    // write AO[b][tq][h*64+d]
    #pragma unroll
    for (int i = 0; i < 4; i++) {
        int tq = t0 + ty * 4 + i;
        float4 o = make_float4(acco[i][0], acco[i][1], acco[i][2], acco[i][3]);
        *(float4*)&AO[((size_t)(b * SEQ + tq)) * HID + h * HDIM + tx * 4] = o;
    }
}

// ---------------- host ----------------
extern "C" void kernel_launch(void* const* d_in, const int* in_sizes, int n_in,
                              void* d_out, int out_size) {
    const float* x    = (const float*)d_in[0];
    const float* Wq   = (const float*)d_in[1];
    const float* Wk   = (const float*)d_in[2];
    const float* Wv   = (const float*)d_in[3];
    const float* cb   = (const float*)d_in[4];
    const float* rb   = (const float*)d_in[5];
    const float* Wrel = (const float*)d_in[6];
    const float* brel = (const float*)d_in[7];
    const float* Wo   = (const float*)d_in[8];
    const float* bo   = (const float*)d_in[9];
    float* out = (float*)d_out;

    float *qc, *qr, *kt, *vt, *rel, *ao, *rwint;
    cudaGetSymbolAddress((void**)&qc,    g_qc);
    cudaGetSymbolAddress((void**)&qr,    g_qr);
    cudaGetSymbolAddress((void**)&kt,    g_k);
    cudaGetSymbolAddress((void**)&vt,    g_v);
    cudaGetSymbolAddress((void**)&rel,   g_rel);
    cudaGetSymbolAddress((void**)&ao,    g_ao);
    cudaGetSymbolAddress((void**)&rwint, g_rwint);

    // Rwin^T (64 x 384)
    rwin_kernel<<<(64 * NRELP + 255) / 256, 256>>>(Wrel, brel, rwint);

    // QKV projections (M=4096, N=1024, K=1024)
    sgemm_kernel<<<dim3(8, 32), 256>>>(x, EMB, Wq, HID, qc, qr, cb, rb,
                                       BATCH * SEQ, HID, EMB, 3);
    sgemm_kernel<<<dim3(8, 32), 256>>>(x, EMB, Wk, HID, kt, nullptr, nullptr, nullptr,
                                       BATCH * SEQ, HID, EMB, 2);
    sgemm_kernel<<<dim3(8, 32), 256>>>(x, EMB, Wv, HID, vt, nullptr, nullptr, nullptr,
                                       BATCH * SEQ, HID, EMB, 2);

    // REL = Qr @ Rwin^T  (M=65536, N=384, K=64)
    sgemm_kernel<<<dim3(NRELP / 128, (BATCH * HEADS * SEQ) / 128), 256>>>(
        qr, HDIM, rwint, NRELP, rel, nullptr, nullptr, nullptr,
        BATCH * HEADS * SEQ, NRELP, HDIM, 0);

    // windowed attention
    size_t attn_smem = (size_t)ATTN_SMEM_FLOATS * sizeof(float);
    cudaFuncSetAttribute(attn_kernel, cudaFuncAttributeMaxDynamicSharedMemorySize,
                         (int)attn_smem);
    attn_kernel<<<dim3(SEQ / TQ, HEADS, BATCH), 256, attn_smem>>>(qc, kt, vt, rel, ao);

    // output projection: out = AO @ Wo + bo
    sgemm_kernel<<<dim3(8, 32), 256>>>(ao, HID, Wo, EMB, out, nullptr, bo, nullptr,
                                       BATCH * SEQ, EMB, HID, 1);
}

// round 5
// speedup vs baseline: 1.9463x; 1.9463x over previous
#include <cuda_runtime.h>
#include <cuda_bf16.h>
#include <stdint.h>
#include <math.h>

// Problem constants
#define BATCH 4
#define SEQ   1024
#define EMB   1024
#define HEADS 16
#define HDIM  64
#define HID   1024            // HEADS*HDIM
#define WIN   128             // half-window
#define NREL  257             // 2*WIN+1
#define NRELP 384             // padded to multiple of 128 for GEMM

// ---------------- scratch (no cudaMalloc allowed) ----------------
__device__ float g_qc[(size_t)BATCH*HEADS*SEQ*HDIM];   // q + content_bias, [b][h][t][d]
__device__ float g_qr[(size_t)BATCH*HEADS*SEQ*HDIM];   // q + relative_bias
__device__ float g_k [(size_t)BATCH*HEADS*SEQ*HDIM];
__device__ float g_v [(size_t)BATCH*HEADS*SEQ*HDIM];
__device__ float g_rel[(size_t)BATCH*HEADS*SEQ*NRELP]; // REL[b,h,t,u]
__device__ float g_ao[(size_t)BATCH*SEQ*HID];          // attention output, [b][t][h*64+d]
__device__ float g_rwint[64*NRELP];                    // RwinT[d][u]

// tf32 round: cvt.rna.tf32.f32 needs a .b32 destination. The result bit-pattern
// is a valid fp32 value (low mantissa bits zeroed), reinterpret back to float.
__device__ __forceinline__ float to_tf32(float x) {
    unsigned int r;
    asm("cvt.rna.tf32.f32 %0, %1;" : "=r"(r) : "f"(x));
    return __uint_as_float(r);
}

// ---------------- Rwin precompute ----------------
__global__ void rwin_kernel(const float* __restrict__ W_rel,
                            const float* __restrict__ b_rel,
                            float* __restrict__ RwinT) {
    int gid = blockIdx.x * blockDim.x + threadIdx.x;
    if (gid >= 64 * NRELP) return;
    int u = gid % NRELP;
    int d = gid / NRELP;
    float out = 0.0f;
    if (u < NREL) {
        float pos = (float)(u - WIN);
        float s = b_rel[d];
        #pragma unroll 8
        for (int f = 0; f < 32; f++) {
            float inv = powf(10000.0f, -(2.0f * (float)f) / 64.0f);
            float a = pos * inv;
            s += sinf(a) * W_rel[f * 64 + d];
            s += cosf(a) * W_rel[(f + 32) * 64 + d];
        }
        out = s;
    }
    RwinT[d * NRELP + u] = out;
}

// ---------------- tf32 tensor-core GEMM ----------------
// Block tile 128x128, K-step 16. 256 threads = 8 warps, warp tile 64x32.
// mma.sync.m16n8k8.tf32; k-slot permutation consistent between A and B
// (slot q <-> phys 2q, slot q+4 <-> phys 2q+1): dot products commute.
// modes: 0 rowmajor C (ld=N); 1 rowmajor C + bias1[n]; 2 bhtd layout C;
//        3 bhtd layout, C = acc + bias1[n], C2 = acc + bias2[n]
#define ASTR 18
#define BSTR 132

__device__ __forceinline__ void mma8(float c[4], float2 alo, float2 ahi, float b0, float b1) {
    asm volatile(
        "mma.sync.aligned.m16n8k8.row.col.f32.tf32.tf32.f32 "
        "{%0,%1,%2,%3}, {%4,%5,%6,%7}, {%8,%9}, {%0,%1,%2,%3};"
        : "+f"(c[0]), "+f"(c[1]), "+f"(c[2]), "+f"(c[3])
        : "r"(__float_as_uint(alo.x)), "r"(__float_as_uint(ahi.x)),
          "r"(__float_as_uint(alo.y)), "r"(__float_as_uint(ahi.y)),
          "r"(__float_as_uint(b0)),   "r"(__float_as_uint(b1)));
}

__global__ void __launch_bounds__(256, 2)
gemm_tf32(const float* __restrict__ A, int lda,
          const float* __restrict__ B, int ldb,
          float* __restrict__ C, float* __restrict__ C2,
          const float* __restrict__ bias1,
          const float* __restrict__ bias2,
          int M, int N, int K, int mode) {
    __shared__ float As[128 * ASTR];   // [m][k] k-padded
    __shared__ float Bs[16 * BSTR];    // [k][n] n-padded

    int tid = threadIdx.x;
    int wid = tid >> 5, lane = tid & 31;
    int lr = lane >> 2, lq = lane & 3;
    int wm = wid & 1, wn = wid >> 1;
    int m0 = blockIdx.y * 128, n0 = blockIdx.x * 128;

    float acc[4][4][4];
    #pragma unroll
    for (int mt = 0; mt < 4; mt++)
        #pragma unroll
        for (int nt = 0; nt < 4; nt++)
            #pragma unroll
            for (int r = 0; r < 4; r++) acc[mt][nt][r] = 0.0f;

    for (int k0 = 0; k0 < K; k0 += 16) {
        __syncthreads();
        #pragma unroll
        for (int l = 0; l < 2; l++) {
            int fidx = tid + 256 * l;
            int m = fidx >> 2, kc = (fidx & 3) << 2;
            float4 v = *(const float4*)(A + (size_t)(m0 + m) * lda + k0 + kc);
            float* p = &As[m * ASTR + kc];
            p[0] = to_tf32(v.x); p[1] = to_tf32(v.y);
            p[2] = to_tf32(v.z); p[3] = to_tf32(v.w);
        }
        #pragma unroll
        for (int l = 0; l < 2; l++) {
            int fidx = tid + 256 * l;
            int k = fidx >> 5, nc = (fidx & 31) << 2;
            float4 v = *(const float4*)(B + (size_t)(k0 + k) * ldb + n0 + nc);
            float* p = &Bs[k * BSTR + nc];
            p[0] = to_tf32(v.x); p[1] = to_tf32(v.y);
            p[2] = to_tf32(v.z); p[3] = to_tf32(v.w);
        }
        __syncthreads();

        #pragma unroll
        for (int k8 = 0; k8 < 2; k8++) {
            int kb = k8 * 8 + 2 * lq;
            float2 av[4][2];
            #pragma unroll
            for (int mt = 0; mt < 4; mt++) {
                int r = wm * 64 + mt * 16 + lr;
                av[mt][0] = *(const float2*)&As[r * ASTR + kb];
                av[mt][1] = *(const float2*)&As[(r + 8) * ASTR + kb];
            }
            float bx[4], by[4];
            #pragma unroll
            for (int nt = 0; nt < 4; nt++) {
                int cc = wn * 32 + nt * 8 + lr;
                bx[nt] = Bs[kb * BSTR + cc];
                by[nt] = Bs[(kb + 1) * BSTR + cc];
            }
            #pragma unroll
            for (int mt = 0; mt < 4; mt++)
                #pragma unroll
                for (int nt = 0; nt < 4; nt++)
                    mma8(acc[mt][nt], av[mt][0], av[mt][1], bx[nt], by[nt]);
        }
    }

    // epilogue: c0 (row,col), c1 (row,col+1), c2 (row+8,col), c3 (row+8,col+1)
    #pragma unroll
    for (int mt = 0; mt < 4; mt++) {
        #pragma unroll
        for (int nt = 0; nt < 4; nt++) {
            int row = m0 + wm * 64 + mt * 16 + lr;
            int col = n0 + wn * 32 + nt * 8 + 2 * lq;
            float c0 = acc[mt][nt][0], c1 = acc[mt][nt][1];
            float c2 = acc[mt][nt][2], c3 = acc[mt][nt][3];
            if (mode == 0) {
                *(float2*)&C[(size_t)row * N + col] = make_float2(c0, c1);
                *(float2*)&C[(size_t)(row + 8) * N + col] = make_float2(c2, c3);
            } else if (mode == 1) {
                float2 bb = *(const float2*)&bias1[col];
                *(float2*)&C[(size_t)row * N + col] = make_float2(c0 + bb.x, c1 + bb.y);
                *(float2*)&C[(size_t)(row + 8) * N + col] = make_float2(c2 + bb.x, c3 + bb.y);
            } else {
                int b = row >> 10, t = row & 1023;
                int hh = col >> 6, dd = col & 63;
                size_t base = (((size_t)(b * HEADS + hh)) << 16) + dd;
                if (mode == 2) {
                    *(float2*)&C[base + (size_t)t * 64] = make_float2(c0, c1);
                    *(float2*)&C[base + (size_t)(t + 8) * 64] = make_float2(c2, c3);
                } else {
                    float2 cbv = *(const float2*)&bias1[col];
                    float2 rbv = *(const float2*)&bias2[col];
                    *(float2*)&C[base + (size_t)t * 64]  = make_float2(c0 + cbv.x, c1 + cbv.y);
                    *(float2*)&C[base + (size_t)(t + 8) * 64] = make_float2(c2 + cbv.x, c3 + cbv.y);
                    *(float2*)&C2[base + (size_t)t * 64] = make_float2(c0 + rbv.x, c1 + rbv.y);
                    *(float2*)&C2[base + (size_t)(t + 8) * 64] = make_float2(c2 + rbv.x, c3 + rbv.y);
                }
            }
        }
    }
}

// ---------------- windowed attention (unchanged, fp32) ----------------
#define TQ   64
#define SPAN 320        // TQ + 2*WIN
#define SP   328        // padded Ssm row
#define DP   68         // padded 64-wide rows
#define ATTN_SMEM_FLOATS (2 * 64 * DP + 64 * SP)

__global__ void __launch_bounds__(256, 1)
attn_kernel(const float* __restrict__ QC,
            const float* __restrict__ KT,
            const float* __restrict__ VT,
            const float* __restrict__ REL,
            float* __restrict__ AO) {
    extern __shared__ float sm[];
    float* Qst = sm;                  // [64][DP]  Qst[d][t]
    float* Kst = sm + 64 * DP;        // [64][DP]  Kst[d][j]; reused as Vs[j][d]
    float* Ssm = sm + 2 * 64 * DP;    // [64][SP]

    int tid = threadIdx.x;
    int tx = tid & 15, ty = tid >> 4;
    int t0 = blockIdx.x * TQ;
    int h = blockIdx.y, b = blockIdx.z;
    size_t bh = (size_t)(b * HEADS + h);
    const float* qb = QC + (bh << 16) + (size_t)t0 * HDIM;
    const float* kb = KT + (bh << 16);
    const float* vb = VT + (bh << 16);
    const float* relb = REL + (bh * SEQ + t0) * NRELP;

    #pragma unroll
    for (int l = 0; l < 4; l++) {
        int fidx = tid + l * 256;
        int t = fidx >> 4;
        int d = (fidx & 15) << 2;
        float4 v = *(const float4*)(qb + t * HDIM + d);
        Qst[(d + 0) * DP + t] = v.x;
        Qst[(d + 1) * DP + t] = v.y;
        Qst[(d + 2) * DP + t] = v.z;
        Qst[(d + 3) * DP + t] = v.w;
    }

    for (int c = 0; c < 5; c++) {
        int j0 = t0 - WIN + c * 64;
        __syncthreads();
        #pragma unroll
        for (int l = 0; l < 4; l++) {
            int fidx = tid + l * 256;
            int jl = fidx >> 4;
            int d = (fidx & 15) << 2;
            int jg = j0 + jl;
            float4 v = make_float4(0.f, 0.f, 0.f, 0.f);
            if (jg >= 0 && jg < SEQ) v = *(const float4*)(kb + (size_t)jg * HDIM + d);
            Kst[(d + 0) * DP + jl] = v.x;
            Kst[(d + 1) * DP + jl] = v.y;
            Kst[(d + 2) * DP + jl] = v.z;
            Kst[(d + 3) * DP + jl] = v.w;
        }
        __syncthreads();

        float acc[4][4];
        #pragma unroll
        for (int i = 0; i < 4; i++)
            #pragma unroll
            for (int j = 0; j < 4; j++) acc[i][j] = 0.0f;

        #pragma unroll 8
        for (int kk = 0; kk < 64; kk++) {
            float4 a = *(float4*)&Qst[kk * DP + ty * 4];
            float4 bb = *(float4*)&Kst[kk * DP + tx * 4];
            float av[4] = {a.x, a.y, a.z, a.w};
            float bv[4] = {bb.x, bb.y, bb.z, bb.w};
            #pragma unroll
            for (int i = 0; i < 4; i++)
                #pragma unroll
                for (int j = 0; j < 4; j++) acc[i][j] += av[i] * bv[j];
        }

        #pragma unroll
        for (int i = 0; i < 4; i++) {
            int t = ty * 4 + i;
            int tq = t0 + t;
            #pragma unroll
            for (int j = 0; j < 4; j++) {
                int jl = tx * 4 + j;
                int jg = j0 + jl;
                int u = tq - jg + WIN;
                float val = -1e30f;
                if (jg >= 0 && jg < SEQ && u >= 0 && u < NREL)
                    val = (acc[i][j] + relb[(size_t)t * NRELP + u]) * 0.03125f;
                Ssm[t * SP + c * 64 + jl] = val;
            }
        }
    }
    __syncthreads();

    {
        int w = tid >> 5, lane = tid & 31;
        for (int t = w * 8; t < w * 8 + 8; t++) {
            float* row = Ssm + t * SP;
            float m = -1e30f;
            for (int idx = lane; idx < SPAN; idx += 32) m = fmaxf(m, row[idx]);
            #pragma unroll
            for (int o = 16; o > 0; o >>= 1) m = fmaxf(m, __shfl_xor_sync(0xffffffffu, m, o));
            float s = 0.0f;
            for (int idx = lane; idx < SPAN; idx += 32) {
                float e = __expf(row[idx] - m);
                row[idx] = e;
                s += e;
            }
            #pragma unroll
            for (int o = 16; o > 0; o >>= 1) s += __shfl_xor_sync(0xffffffffu, s, o);
            float inv = 1.0f / s;
            for (int idx = lane; idx < SPAN; idx += 32) row[idx] *= inv;
        }
    }

    float acco[4][4];
    #pragma unroll
    for (int i = 0; i < 4; i++)
        #pragma unroll
        for (int j = 0; j < 4; j++) acco[i][j] = 0.0f;

    float* Vs = Kst;
    for (int c = 0; c < 5; c++) {
        int j0 = t0 - WIN + c * 64;
        __syncthreads();
        #pragma unroll
        for (int l = 0; l < 4; l++) {
            int fidx = tid + l * 256;
            int jl = fidx >> 4;
            int d = (fidx & 15) << 2;
            int jg = j0 + jl;
            float4 v = make_float4(0.f, 0.f, 0.f, 0.f);
            if (jg >= 0 && jg < SEQ) v = *(const float4*)(vb + (size_t)jg * HDIM + d);
            *(float4*)&Vs[jl * DP + d] = v;
        }
        __syncthreads();

        #pragma unroll 8
        for (int jk = 0; jk < 64; jk++) {
            float a0 = Ssm[(ty * 4 + 0) * SP + c * 64 + jk];
            float a1 = Ssm[(ty * 4 + 1) * SP + c * 64 + jk];
            float a2 = Ssm[(ty * 4 + 2) * SP + c * 64 + jk];
            float a3 = Ssm[(ty * 4 + 3) * SP + c * 64 + jk];
            float4 bb = *(float4*)&Vs[jk * DP + tx * 4];
            float bv[4] = {bb.x, bb.y, bb.z, bb.w};
            float av[4] = {a0, a1, a2, a3};
            #pragma unroll
            for (int i = 0; i < 4; i++)
                #pragma unroll
                for (int j = 0; j < 4; j++) acco[i][j] += av[i] * bv[j];
        }
    }

    #pragma unroll
    for (int i = 0; i < 4; i++) {
        int tq = t0 + ty * 4 + i;
        float4 o = make_float4(acco[i][0], acco[i][1], acco[i][2], acco[i][3]);
        *(float4*)&AO[((size_t)(b * SEQ + tq)) * HID + h * HDIM + tx * 4] = o;
    }
}

// ---------------- host ----------------
extern "C" void kernel_launch(void* const* d_in, const int* in_sizes, int n_in,
                              void* d_out, int out_size) {
    const float* x    = (const float*)d_in[0];
    const float* Wq   = (const float*)d_in[1];
    const float* Wk   = (const float*)d_in[2];
    const float* Wv   = (const float*)d_in[3];
    const float* cb   = (const float*)d_in[4];
    const float* rb   = (const float*)d_in[5];
    const float* Wrel = (const float*)d_in[6];
    const float* brel = (const float*)d_in[7];
    const float* Wo   = (const float*)d_in[8];
    const float* bo   = (const float*)d_in[9];
    float* out = (float*)d_out;

    float *qc, *qr, *kt, *vt, *rel, *ao, *rwint;
    cudaGetSymbolAddress((void**)&qc,    g_qc);
    cudaGetSymbolAddress((void**)&qr,    g_qr);
    cudaGetSymbolAddress((void**)&kt,    g_k);
    cudaGetSymbolAddress((void**)&vt,    g_v);
    cudaGetSymbolAddress((void**)&rel,   g_rel);
    cudaGetSymbolAddress((void**)&ao,    g_ao);
    cudaGetSymbolAddress((void**)&rwint, g_rwint);

    // Rwin^T (64 x 384)
    rwin_kernel<<<(64 * NRELP + 255) / 256, 256>>>(Wrel, brel, rwint);

    // QKV projections (M=4096, N=1024, K=1024), tensor core tf32
    gemm_tf32<<<dim3(8, 32), 256>>>(x, EMB, Wq, HID, qc, qr, cb, rb,
                                    BATCH * SEQ, HID, EMB, 3);
    gemm_tf32<<<dim3(8, 32), 256>>>(x, EMB, Wk, HID, kt, nullptr, nullptr, nullptr,
                                    BATCH * SEQ, HID, EMB, 2);
    gemm_tf32<<<dim3(8, 32), 256>>>(x, EMB, Wv, HID, vt, nullptr, nullptr, nullptr,
                                    BATCH * SEQ, HID, EMB, 2);

    // REL = Qr @ Rwin^T  (M=65536, N=384, K=64)
    gemm_tf32<<<dim3(NRELP / 128, (BATCH * HEADS * SEQ) / 128), 256>>>(
        qr, HDIM, rwint, NRELP, rel, nullptr, nullptr, nullptr,
        BATCH * HEADS * SEQ, NRELP, HDIM, 0);

    // windowed attention (fp32)
    size_t attn_smem = (size_t)ATTN_SMEM_FLOATS * sizeof(float);
    cudaFuncSetAttribute(attn_kernel, cudaFuncAttributeMaxDynamicSharedMemorySize,
                         (int)attn_smem);
    attn_kernel<<<dim3(SEQ / TQ, HEADS, BATCH), 256, attn_smem>>>(qc, kt, vt, rel, ao);

    // output projection: out = AO @ Wo + bo
    gemm_tf32<<<dim3(8, 32), 256>>>(ao, HID, Wo, EMB, out, nullptr, bo, nullptr,
                                    BATCH * SEQ, EMB, HID, 1);
}

// round 6
// speedup vs baseline: 2.2738x; 1.1683x over previous
#include <cuda_runtime.h>
#include <cuda_bf16.h>
#include <stdint.h>
#include <math.h>

// Problem constants
#define BATCH 4
#define SEQ   1024
#define EMB   1024
#define HEADS 16
#define HDIM  64
#define HID   1024
#define WIN   128             // half-window
#define NREL  257             // 2*WIN+1
#define SCALE 0.03125f

// ---------------- scratch ----------------
__device__ float g_qc[(size_t)BATCH*HEADS*SEQ*HDIM];   // [b][h][t][d]
__device__ float g_qr[(size_t)BATCH*HEADS*SEQ*HDIM];
__device__ float g_k [(size_t)BATCH*HEADS*SEQ*HDIM];
__device__ float g_v [(size_t)BATCH*HEADS*SEQ*HDIM];
__device__ float g_ao[(size_t)BATCH*SEQ*HID];          // [b][t][h*64+d]
__device__ float g_rwint[64*NREL];                     // RwinT[d][u]

__device__ __forceinline__ float to_tf32(float x) {
    unsigned int r;
    asm("cvt.rna.tf32.f32 %0, %1;" : "=r"(r) : "f"(x));
    return __uint_as_float(r);
}

// ---------------- Rwin precompute: RwinT[d][u], stride NREL ----------------
__global__ void rwin_kernel(const float* __restrict__ W_rel,
                            const float* __restrict__ b_rel,
                            float* __restrict__ RwinT) {
    int gid = blockIdx.x * blockDim.x + threadIdx.x;
    if (gid >= 64 * NREL) return;
    int u = gid % NREL;
    int d = gid / NREL;
    float pos = (float)(u - WIN);
    float s = b_rel[d];
    #pragma unroll 8
    for (int f = 0; f < 32; f++) {
        float inv = powf(10000.0f, -(2.0f * (float)f) / 64.0f);
        float a = pos * inv;
        s += sinf(a) * W_rel[f * 64 + d];
        s += cosf(a) * W_rel[(f + 32) * 64 + d];
    }
    RwinT[d * NREL + u] = s;
}

// ---------------- tf32 tensor-core MMA primitive (validated in R5) ---------
// c0=(row,col) c1=(row,col+1) c2=(row+8,col) c3=(row+8,col+1)
// A[m][k] frag: alo=A[row][kb..kb+1], ahi=A[row+8][kb..kb+1], kb=k8*8+2*lq
// B[k][n] frag: bx=B[kb][colbase+lr], by=B[kb+1][colbase+lr]
__device__ __forceinline__ void mma8(float c[4], float2 alo, float2 ahi, float b0, float b1) {
    asm volatile(
        "mma.sync.aligned.m16n8k8.row.col.f32.tf32.tf32.f32 "
        "{%0,%1,%2,%3}, {%4,%5,%6,%7}, {%8,%9}, {%0,%1,%2,%3};"
        : "+f"(c[0]), "+f"(c[1]), "+f"(c[2]), "+f"(c[3])
        : "r"(__float_as_uint(alo.x)), "r"(__float_as_uint(ahi.x)),
          "r"(__float_as_uint(alo.y)), "r"(__float_as_uint(ahi.y)),
          "r"(__float_as_uint(b0)),   "r"(__float_as_uint(b1)));
}

// ---------------- tf32 GEMM (unchanged from R5) ----------------
#define ASTR 18
#define BSTR 132

__global__ void __launch_bounds__(256, 2)
gemm_tf32(const float* __restrict__ A, int lda,
          const float* __restrict__ B, int ldb,
          float* __restrict__ C, float* __restrict__ C2,
          const float* __restrict__ bias1,
          const float* __restrict__ bias2,
          int M, int N, int K, int mode) {
    __shared__ float As[128 * ASTR];
    __shared__ float Bs[16 * BSTR];

    int tid = threadIdx.x;
    int wid = tid >> 5, lane = tid & 31;
    int lr = lane >> 2, lq = lane & 3;
    int wm = wid & 1, wn = wid >> 1;
    int m0 = blockIdx.y * 128, n0 = blockIdx.x * 128;

    float acc[4][4][4];
    #pragma unroll
    for (int mt = 0; mt < 4; mt++)
        #pragma unroll
        for (int nt = 0; nt < 4; nt++)
            #pragma unroll
            for (int r = 0; r < 4; r++) acc[mt][nt][r] = 0.0f;

    for (int k0 = 0; k0 < K; k0 += 16) {
        __syncthreads();
        #pragma unroll
        for (int l = 0; l < 2; l++) {
            int fidx = tid + 256 * l;
            int m = fidx >> 2, kc = (fidx & 3) << 2;
            float4 v = *(const float4*)(A + (size_t)(m0 + m) * lda + k0 + kc);
            float* p = &As[m * ASTR + kc];
            p[0] = to_tf32(v.x); p[1] = to_tf32(v.y);
            p[2] = to_tf32(v.z); p[3] = to_tf32(v.w);
        }
        #pragma unroll
        for (int l = 0; l < 2; l++) {
            int fidx = tid + 256 * l;
            int k = fidx >> 5, nc = (fidx & 31) << 2;
            float4 v = *(const float4*)(B + (size_t)(k0 + k) * ldb + n0 + nc);
            float* p = &Bs[k * BSTR + nc];
            p[0] = to_tf32(v.x); p[1] = to_tf32(v.y);
            p[2] = to_tf32(v.z); p[3] = to_tf32(v.w);
        }
        __syncthreads();

        #pragma unroll
        for (int k8 = 0; k8 < 2; k8++) {
            int kb = k8 * 8 + 2 * lq;
            float2 av[4][2];
            #pragma unroll
            for (int mt = 0; mt < 4; mt++) {
                int r = wm * 64 + mt * 16 + lr;
                av[mt][0] = *(const float2*)&As[r * ASTR + kb];
                av[mt][1] = *(const float2*)&As[(r + 8) * ASTR + kb];
            }
            float bx[4], by[4];
            #pragma unroll
            for (int nt = 0; nt < 4; nt++) {
                int cc = wn * 32 + nt * 8 + lr;
                bx[nt] = Bs[kb * BSTR + cc];
                by[nt] = Bs[(kb + 1) * BSTR + cc];
            }
            #pragma unroll
            for (int mt = 0; mt < 4; mt++)
                #pragma unroll
                for (int nt = 0; nt < 4; nt++)
                    mma8(acc[mt][nt], av[mt][0], av[mt][1], bx[nt], by[nt]);
        }
    }

    #pragma unroll
    for (int mt = 0; mt < 4; mt++) {
        #pragma unroll
        for (int nt = 0; nt < 4; nt++) {
            int row = m0 + wm * 64 + mt * 16 + lr;
            int col = n0 + wn * 32 + nt * 8 + 2 * lq;
            float c0 = acc[mt][nt][0], c1 = acc[mt][nt][1];
            float c2 = acc[mt][nt][2], c3 = acc[mt][nt][3];
            if (mode == 0) {
                *(float2*)&C[(size_t)row * N + col] = make_float2(c0, c1);
                *(float2*)&C[(size_t)(row + 8) * N + col] = make_float2(c2, c3);
            } else if (mode == 1) {
                float2 bb = *(const float2*)&bias1[col];
                *(float2*)&C[(size_t)row * N + col] = make_float2(c0 + bb.x, c1 + bb.y);
                *(float2*)&C[(size_t)(row + 8) * N + col] = make_float2(c2 + bb.x, c3 + bb.y);
            } else {
                int b = row >> 10, t = row & 1023;
                int hh = col >> 6, dd = col & 63;
                size_t base = (((size_t)(b * HEADS + hh)) << 16) + dd;
                if (mode == 2) {
                    *(float2*)&C[base + (size_t)t * 64] = make_float2(c0, c1);
                    *(float2*)&C[base + (size_t)(t + 8) * 64] = make_float2(c2, c3);
                } else {
                    float2 cbv = *(const float2*)&bias1[col];
                    float2 rbv = *(const float2*)&bias2[col];
                    *(float2*)&C[base + (size_t)t * 64]  = make_float2(c0 + cbv.x, c1 + cbv.y);
                    *(float2*)&C[base + (size_t)(t + 8) * 64] = make_float2(c2 + cbv.x, c3 + cbv.y);
                    *(float2*)&C2[base + (size_t)t * 64] = make_float2(c0 + rbv.x, c1 + rbv.y);
                    *(float2*)&C2[base + (size_t)(t + 8) * 64] = make_float2(c2 + rbv.x, c3 + rbv.y);
                }
            }
        }
    }
}

// ---------------- windowed attention, all matmuls on mma, REL fused --------
// 64-query tile per (b,h). 256 threads = 8 warps: wm=wid&3 (m16 tile), wn=wid>>2.
#define TQ    64
#define SPAN  320
#define SP    328   // Ssm row stride
#define AQP   68    // Qc/Qr row stride
#define RWP   272   // Rwin row stride ([d][u], u padded 272)
#define PPW   272   // Psm row stride
#define KVP   68
#define OFF_QC 0
#define OFF_QR 4352
#define OFF_RW 8704                      // 64*272 -> ends 26112
#define OFF_SS 4352                      // overlays QR+RW after Prel phase (needs 64*328=20992 <= 21760)
#define OFF_PS 26112                     // 64*272 -> ends 43520
#define OFF_KV 43520                     // 64*68  -> ends 47872
#define ATTN_FLOATS 47872

__global__ void __launch_bounds__(256, 1)
attn_mma_kernel(const float* __restrict__ QC, const float* __restrict__ QR,
                const float* __restrict__ K,  const float* __restrict__ V,
                const float* __restrict__ RwinT, float* __restrict__ AO) {
    extern __shared__ float sm[];
    int tid = threadIdx.x;
    int wid = tid >> 5, lane = tid & 31;
    int lr = lane >> 2, lq = lane & 3;
    int wm = wid & 3, wn = wid >> 2;
    int t0 = blockIdx.x * TQ, h = blockIdx.y, b = blockIdx.z;
    size_t bh = (size_t)(b * HEADS + h);
    const float* qcb = QC + (bh << 16) + (size_t)t0 * 64;
    const float* qrb = QR + (bh << 16) + (size_t)t0 * 64;
    const float* kb  = K  + (bh << 16);
    const float* vb  = V  + (bh << 16);
    int j0base = t0 - WIN;

    // ---- load Qc, Qr (row-major [t][d], tf32) ----
    #pragma unroll
    for (int l = 0; l < 4; l++) {
        int fidx = tid + 256 * l;
        int t = fidx >> 4, d = (fidx & 15) << 2;
        float4 a = *(const float4*)(qcb + t * 64 + d);
        float4 r = *(const float4*)(qrb + t * 64 + d);
        float* pc = &sm[OFF_QC + t * AQP + d];
        pc[0] = to_tf32(a.x); pc[1] = to_tf32(a.y); pc[2] = to_tf32(a.z); pc[3] = to_tf32(a.w);
        float* pr = &sm[OFF_QR + t * AQP + d];
        pr[0] = to_tf32(r.x); pr[1] = to_tf32(r.y); pr[2] = to_tf32(r.z); pr[3] = to_tf32(r.w);
    }
    // ---- load Rwin [d][u], zero-pad u in [257,272) ----
    for (int idx = tid; idx < 64 * RWP; idx += 256) {
        int d = idx / RWP, u = idx - d * RWP;
        float v = (u < NREL) ? RwinT[d * NREL + u] : 0.0f;
        sm[OFF_RW + d * RWP + u] = to_tf32(v);
    }
    __syncthreads();

    // ---- Prel = Qr @ Rwin  (64 x 272, K=64) -> Psm ----
    {
        float pc[17][4];
        #pragma unroll
        for (int nt = 0; nt < 17; nt++)
            #pragma unroll
            for (int r = 0; r < 4; r++) pc[nt][r] = 0.0f;
        #pragma unroll
        for (int k8 = 0; k8 < 8; k8++) {
            int kbi = k8 * 8 + 2 * lq;
            int r = wm * 16 + lr;
            float2 alo = *(const float2*)&sm[OFF_QR + r * AQP + kbi];
            float2 ahi = *(const float2*)&sm[OFF_QR + (r + 8) * AQP + kbi];
            #pragma unroll
            for (int nt = 0; nt < 17; nt++) {
                int cc = wn * 136 + nt * 8 + lr;
                float bx = sm[OFF_RW + kbi * RWP + cc];
                float by = sm[OFF_RW + (kbi + 1) * RWP + cc];
                mma8(pc[nt], alo, ahi, bx, by);
            }
        }
        __syncthreads();   // all Rwin/Qr reads done before Psm write? (Psm is distinct region; sync protects nothing here but orders the next overlay) -- keep for safety
        #pragma unroll
        for (int nt = 0; nt < 17; nt++) {
            int cl = wn * 136 + nt * 8 + 2 * lq;
            int m = wm * 16 + lr;
            sm[OFF_PS + m * PPW + cl]           = pc[nt][0];
            sm[OFF_PS + m * PPW + cl + 1]       = pc[nt][1];
            sm[OFF_PS + (m + 8) * PPW + cl]     = pc[nt][2];
            sm[OFF_PS + (m + 8) * PPW + cl + 1] = pc[nt][3];
        }
    }
    __syncthreads();   // Prel phase done: Qr+Rwin region becomes Ssm

    // ---- scores: S = Qc @ K^T + gather(Prel), 5 chunks of 64 keys ----
    for (int c = 0; c < 5; c++) {
        int j0 = j0base + c * 64;
        __syncthreads();  // prior chunk's KV reads complete
        #pragma unroll
        for (int l = 0; l < 4; l++) {
            int fidx = tid + 256 * l;
            int jl = fidx >> 4, d = (fidx & 15) << 2;
            int jg = j0 + jl;
            float4 v = make_float4(0.f, 0.f, 0.f, 0.f);
            if (jg >= 0 && jg < SEQ) v = *(const float4*)(kb + (size_t)jg * 64 + d);
            sm[OFF_KV + (d + 0) * KVP + jl] = to_tf32(v.x);
            sm[OFF_KV + (d + 1) * KVP + jl] = to_tf32(v.y);
            sm[OFF_KV + (d + 2) * KVP + jl] = to_tf32(v.z);
            sm[OFF_KV + (d + 3) * KVP + jl] = to_tf32(v.w);
        }
        __syncthreads();

        float sc[4][4];
        #pragma unroll
        for (int nt = 0; nt < 4; nt++)
            #pragma unroll
            for (int r = 0; r < 4; r++) sc[nt][r] = 0.0f;
        #pragma unroll
        for (int k8 = 0; k8 < 8; k8++) {
            int kbi = k8 * 8 + 2 * lq;
            int r = wm * 16 + lr;
            float2 alo = *(const float2*)&sm[OFF_QC + r * AQP + kbi];
            float2 ahi = *(const float2*)&sm[OFF_QC + (r + 8) * AQP + kbi];
            #pragma unroll
            for (int nt = 0; nt < 4; nt++) {
                int cc = wn * 32 + nt * 8 + lr;
                float bx = sm[OFF_KV + kbi * KVP + cc];
                float by = sm[OFF_KV + (kbi + 1) * KVP + cc];
                mma8(sc[nt], alo, ahi, bx, by);
            }
        }
        // epilogue: add Prel diagonal gather, scale, mask -> Ssm
        #pragma unroll
        for (int nt = 0; nt < 4; nt++) {
            int cl = wn * 32 + nt * 8 + 2 * lq;
            #pragma unroll
            for (int e = 0; e < 4; e++) {
                int m  = wm * 16 + lr + (e >> 1) * 8;
                int jl = c * 64 + cl + (e & 1);
                int jg = j0base + jl;
                int u  = m - jl + 256;      // = tq - jg + WIN
                float val = -1e30f;
                if (jg >= 0 && jg < SEQ && u >= 0 && u < NREL)
                    val = (sc[nt][e] + sm[OFF_PS + m * PPW + u]) * SCALE;
                sm[OFF_SS + m * SP + jl] = val;
            }
        }
    }
    __syncthreads();

    // ---- softmax (8 warps x 8 rows), tf32 on normalized write ----
    {
        int w = wid, ln = lane;
        for (int t = w * 8; t < w * 8 + 8; t++) {
            float* row = &sm[OFF_SS + t * SP];
            float m = -1e30f;
            for (int idx = ln; idx < SPAN; idx += 32) m = fmaxf(m, row[idx]);
            #pragma unroll
            for (int o = 16; o > 0; o >>= 1) m = fmaxf(m, __shfl_xor_sync(0xffffffffu, m, o));
            float s = 0.0f;
            for (int idx = ln; idx < SPAN; idx += 32) {
                float e = __expf(row[idx] - m);
                row[idx] = e;
                s += e;
            }
            #pragma unroll
            for (int o = 16; o > 0; o >>= 1) s += __shfl_xor_sync(0xffffffffu, s, o);
            float inv = 1.0f / s;
            for (int idx = ln; idx < SPAN; idx += 32) row[idx] = to_tf32(row[idx] * inv);
        }
    }

    // ---- O = P @ V, accumulate over 5 chunks ----
    float ao_[4][4];
    #pragma unroll
    for (int nt = 0; nt < 4; nt++)
        #pragma unroll
        for (int r = 0; r < 4; r++) ao_[nt][r] = 0.0f;

    for (int c = 0; c < 5; c++) {
        int j0 = j0base + c * 64;
        __syncthreads();  // softmax done / prior chunk V reads done
        #pragma unroll
        for (int l = 0; l < 4; l++) {
            int fidx = tid + 256 * l;
            int jl = fidx >> 4, d = (fidx & 15) << 2;
            int jg = j0 + jl;
            float4 v = make_float4(0.f, 0.f, 0.f, 0.f);
            if (jg >= 0 && jg < SEQ) v = *(const float4*)(vb + (size_t)jg * 64 + d);
            float* p = &sm[OFF_KV + jl * KVP + d];
            p[0] = to_tf32(v.x); p[1] = to_tf32(v.y); p[2] = to_tf32(v.z); p[3] = to_tf32(v.w);
        }
        __syncthreads();

        #pragma unroll
        for (int k8 = 0; k8 < 8; k8++) {
            int kbi = k8 * 8 + 2 * lq;
            int r = wm * 16 + lr;
            float2 alo = *(const float2*)&sm[OFF_SS + r * SP + c * 64 + kbi];
            float2 ahi = *(const float2*)&sm[OFF_SS + (r + 8) * SP + c * 64 + kbi];
            #pragma unroll
            for (int nt = 0; nt < 4; nt++) {
                int cc = wn * 32 + nt * 8 + lr;
                float bx = sm[OFF_KV + kbi * KVP + cc];
                float by = sm[OFF_KV + (kbi + 1) * KVP + cc];
                mma8(ao_[nt], alo, ahi, bx, by);
            }
        }
    }

    // ---- write AO[b][t0+m][h*64+n] ----
    #pragma unroll
    for (int nt = 0; nt < 4; nt++) {
        int n = wn * 32 + nt * 8 + 2 * lq;
        int m = wm * 16 + lr;
        size_t o0 = ((size_t)(b * SEQ + t0 + m)) * HID + h * 64 + n;
        size_t o1 = ((size_t)(b * SEQ + t0 + m + 8)) * HID + h * 64 + n;
        *(float2*)&AO[o0] = make_float2(ao_[nt][0], ao_[nt][1]);
        *(float2*)&AO[o1] = make_float2(ao_[nt][2], ao_[nt][3]);
    }
}

// ---------------- host ----------------
extern "C" void kernel_launch(void* const* d_in, const int* in_sizes, int n_in,
                              void* d_out, int out_size) {
    const float* x    = (const float*)d_in[0];
    const float* Wq   = (const float*)d_in[1];
    const float* Wk   = (const float*)d_in[2];
    const float* Wv   = (const float*)d_in[3];
    const float* cb   = (const float*)d_in[4];
    const float* rb   = (const float*)d_in[5];
    const float* Wrel = (const float*)d_in[6];
    const float* brel = (const float*)d_in[7];
    const float* Wo   = (const float*)d_in[8];
    const float* bo   = (const float*)d_in[9];
    float* out = (float*)d_out;

    float *qc, *qr, *kt, *vt, *ao, *rwint;
    cudaGetSymbolAddress((void**)&qc,    g_qc);
    cudaGetSymbolAddress((void**)&qr,    g_qr);
    cudaGetSymbolAddress((void**)&kt,    g_k);
    cudaGetSymbolAddress((void**)&vt,    g_v);
    cudaGetSymbolAddress((void**)&ao,    g_ao);
    cudaGetSymbolAddress((void**)&rwint, g_rwint);

    rwin_kernel<<<(64 * NREL + 255) / 256, 256>>>(Wrel, brel, rwint);

    gemm_tf32<<<dim3(8, 32), 256>>>(x, EMB, Wq, HID, qc, qr, cb, rb,
                                    BATCH * SEQ, HID, EMB, 3);
    gemm_tf32<<<dim3(8, 32), 256>>>(x, EMB, Wk, HID, kt, nullptr, nullptr, nullptr,
                                    BATCH * SEQ, HID, EMB, 2);
    gemm_tf32<<<dim3(8, 32), 256>>>(x, EMB, Wv, HID, vt, nullptr, nullptr, nullptr,
                                    BATCH * SEQ, HID, EMB, 2);

    size_t attn_smem = (size_t)ATTN_FLOATS * sizeof(float);
    cudaFuncSetAttribute(attn_mma_kernel, cudaFuncAttributeMaxDynamicSharedMemorySize,
                         (int)attn_smem);
    attn_mma_kernel<<<dim3(SEQ / TQ, HEADS, BATCH), 256, attn_smem>>>(
        qc, qr, kt, vt, rwint, ao);

    gemm_tf32<<<dim3(8, 32), 256>>>(ao, HID, Wo, EMB, out, nullptr, bo, nullptr,
                                    BATCH * SEQ, EMB, HID, 1);
}

// round 7
// speedup vs baseline: 2.3413x; 1.0297x over previous
#include <cuda_runtime.h>
#include <cuda_bf16.h>
#include <stdint.h>
#include <math.h>

#define BATCH 4
#define SEQ   1024
#define EMB   1024
#define HEADS 16
#define HDIM  64
#define HID   1024
#define WIN   128
#define NREL  257
#define SCALE 0.03125f

// ---------------- scratch ----------------
__device__ float g_qc[(size_t)BATCH*HEADS*SEQ*HDIM];
__device__ float g_qr[(size_t)BATCH*HEADS*SEQ*HDIM];
__device__ float g_k [(size_t)BATCH*HEADS*SEQ*HDIM];
__device__ float g_v [(size_t)BATCH*HEADS*SEQ*HDIM];
__device__ float g_ao[(size_t)BATCH*SEQ*HID];
__device__ float g_rwint[64*NREL];

__device__ __forceinline__ float to_tf32(float x) {
    unsigned int r;
    asm("cvt.rna.tf32.f32 %0, %1;" : "=r"(r) : "f"(x));
    return __uint_as_float(r);
}

// ---------------- Rwin precompute ----------------
__global__ void rwin_kernel(const float* __restrict__ W_rel,
                            const float* __restrict__ b_rel,
                            float* __restrict__ RwinT) {
    int gid = blockIdx.x * blockDim.x + threadIdx.x;
    if (gid >= 64 * NREL) return;
    int u = gid % NREL;
    int d = gid / NREL;
    float pos = (float)(u - WIN);
    float s = b_rel[d];
    #pragma unroll 8
    for (int f = 0; f < 32; f++) {
        float inv = powf(10000.0f, -(2.0f * (float)f) / 64.0f);
        float a = pos * inv;
        s += sinf(a) * W_rel[f * 64 + d];
        s += cosf(a) * W_rel[(f + 32) * 64 + d];
    }
    RwinT[d * NREL + u] = s;
}

// ---------------- mma primitive ----------------
__device__ __forceinline__ void mma8(float c[4], float2 alo, float2 ahi, float b0, float b1) {
    asm volatile(
        "mma.sync.aligned.m16n8k8.row.col.f32.tf32.tf32.f32 "
        "{%0,%1,%2,%3}, {%4,%5,%6,%7}, {%8,%9}, {%0,%1,%2,%3};"
        : "+f"(c[0]), "+f"(c[1]), "+f"(c[2]), "+f"(c[3])
        : "r"(__float_as_uint(alo.x)), "r"(__float_as_uint(ahi.x)),
          "r"(__float_as_uint(alo.y)), "r"(__float_as_uint(ahi.y)),
          "r"(__float_as_uint(b0)),   "r"(__float_as_uint(b1)));
}

#define ASTR 18
#define BSTR 132

__device__ __forceinline__ void sts4_tf32(float* p, float4 v) {
    p[0] = to_tf32(v.x); p[1] = to_tf32(v.y);
    p[2] = to_tf32(v.z); p[3] = to_tf32(v.w);
}

// ---------------- fused QKV GEMM, double-buffered ----------------
// grid (24, 32): which = bx>>3 selects Wq/Wk/Wv; n0 = (bx&7)*128; m0 = by*128.
__global__ void __launch_bounds__(256, 2)
gemm_qkv_tf32(const float* __restrict__ X,
              const float* __restrict__ Wq, const float* __restrict__ Wk,
              const float* __restrict__ Wv,
              const float* __restrict__ cb, const float* __restrict__ rb,
              float* __restrict__ qc, float* __restrict__ qr,
              float* __restrict__ kt, float* __restrict__ vt) {
    __shared__ float As[2][128 * ASTR];
    __shared__ float Bs[2][16 * BSTR];

    int tid = threadIdx.x;
    int wid = tid >> 5, lane = tid & 31;
    int lr = lane >> 2, lq = lane & 3;
    int wm = wid & 1, wn = wid >> 1;
    int which = blockIdx.x >> 3;
    const float* B = (which == 0) ? Wq : ((which == 1) ? Wk : Wv);
    int n0 = (blockIdx.x & 7) * 128;
    int m0 = blockIdx.y * 128;

    int am[2], ak[2], bk[2], bn[2];
    #pragma unroll
    for (int l = 0; l < 2; l++) {
        int fidx = tid + 256 * l;
        am[l] = fidx >> 2;  ak[l] = (fidx & 3) << 2;
        bk[l] = fidx >> 5;  bn[l] = (fidx & 31) << 2;
    }

    float acc[4][4][4];
    #pragma unroll
    for (int mt = 0; mt < 4; mt++)
        #pragma unroll
        for (int nt = 0; nt < 4; nt++)
            #pragma unroll
            for (int r = 0; r < 4; r++) acc[mt][nt][r] = 0.0f;

    float4 pa[2], pb[2];
    #pragma unroll
    for (int l = 0; l < 2; l++) {
        pa[l] = *(const float4*)(X + (size_t)(m0 + am[l]) * EMB + ak[l]);
        pb[l] = *(const float4*)(B + (size_t)bk[l] * HID + n0 + bn[l]);
    }
    #pragma unroll
    for (int l = 0; l < 2; l++) {
        sts4_tf32(&As[0][am[l] * ASTR + ak[l]], pa[l]);
        sts4_tf32(&Bs[0][bk[l] * BSTR + bn[l]], pb[l]);
    }
    __syncthreads();

    for (int ks = 0; ks < 64; ks++) {
        int cur = ks & 1;
        if (ks < 63) {
            int k0 = (ks + 1) * 16;
            #pragma unroll
            for (int l = 0; l < 2; l++) {
                pa[l] = *(const float4*)(X + (size_t)(m0 + am[l]) * EMB + k0 + ak[l]);
                pb[l] = *(const float4*)(B + (size_t)(k0 + bk[l]) * HID + n0 + bn[l]);
            }
        }
        #pragma unroll
        for (int k8 = 0; k8 < 2; k8++) {
            int kb = k8 * 8 + 2 * lq;
            float2 av[4][2];
            #pragma unroll
            for (int mt = 0; mt < 4; mt++) {
                int r = wm * 64 + mt * 16 + lr;
                av[mt][0] = *(const float2*)&As[cur][r * ASTR + kb];
                av[mt][1] = *(const float2*)&As[cur][(r + 8) * ASTR + kb];
            }
            float bx[4], by[4];
            #pragma unroll
            for (int nt = 0; nt < 4; nt++) {
                int cc = wn * 32 + nt * 8 + lr;
                bx[nt] = Bs[cur][kb * BSTR + cc];
                by[nt] = Bs[cur][(kb + 1) * BSTR + cc];
            }
            #pragma unroll
            for (int mt = 0; mt < 4; mt++)
                #pragma unroll
                for (int nt = 0; nt < 4; nt++)
                    mma8(acc[mt][nt], av[mt][0], av[mt][1], bx[nt], by[nt]);
        }
        if (ks < 63) {
            #pragma unroll
            for (int l = 0; l < 2; l++) {
                sts4_tf32(&As[cur ^ 1][am[l] * ASTR + ak[l]], pa[l]);
                sts4_tf32(&Bs[cur ^ 1][bk[l] * BSTR + bn[l]], pb[l]);
            }
        }
        __syncthreads();
    }

    #pragma unroll
    for (int mt = 0; mt < 4; mt++) {
        #pragma unroll
        for (int nt = 0; nt < 4; nt++) {
            int row = m0 + wm * 64 + mt * 16 + lr;
            int col = n0 + wn * 32 + nt * 8 + 2 * lq;
            float c0 = acc[mt][nt][0], c1 = acc[mt][nt][1];
            float c2 = acc[mt][nt][2], c3 = acc[mt][nt][3];
            int b = row >> 10, t = row & 1023;
            int hh = col >> 6, dd = col & 63;
            size_t base = (((size_t)(b * HEADS + hh)) << 16) + dd;
            if (which == 0) {
                float2 cbv = *(const float2*)&cb[col];
                float2 rbv = *(const float2*)&rb[col];
                *(float2*)&qc[base + (size_t)t * 64]       = make_float2(c0 + cbv.x, c1 + cbv.y);
                *(float2*)&qc[base + (size_t)(t + 8) * 64] = make_float2(c2 + cbv.x, c3 + cbv.y);
                *(float2*)&qr[base + (size_t)t * 64]       = make_float2(c0 + rbv.x, c1 + rbv.y);
                *(float2*)&qr[base + (size_t)(t + 8) * 64] = make_float2(c2 + rbv.x, c3 + rbv.y);
            } else if (which == 1) {
                *(float2*)&kt[base + (size_t)t * 64]       = make_float2(c0, c1);
                *(float2*)&kt[base + (size_t)(t + 8) * 64] = make_float2(c2, c3);
            } else {
                *(float2*)&vt[base + (size_t)t * 64]       = make_float2(c0, c1);
                *(float2*)&vt[base + (size_t)(t + 8) * 64] = make_float2(c2, c3);
            }
        }
    }
}

// ---------------- out-proj GEMM, double-buffered: out = A@B + bias ----------
__global__ void __launch_bounds__(256, 2)
gemm_proj_tf32(const float* __restrict__ A, const float* __restrict__ B,
               const float* __restrict__ bias, float* __restrict__ C) {
    __shared__ float As[2][128 * ASTR];
    __shared__ float Bs[2][16 * BSTR];

    int tid = threadIdx.x;
    int wid = tid >> 5, lane = tid & 31;
    int lr = lane >> 2, lq = lane & 3;
    int wm = wid & 1, wn = wid >> 1;
    int n0 = blockIdx.x * 128, m0 = blockIdx.y * 128;

    int am[2], ak[2], bk[2], bn[2];
    #pragma unroll
    for (int l = 0; l < 2; l++) {
        int fidx = tid + 256 * l;
        am[l] = fidx >> 2;  ak[l] = (fidx & 3) << 2;
        bk[l] = fidx >> 5;  bn[l] = (fidx & 31) << 2;
    }

    float acc[4][4][4];
    #pragma unroll
    for (int mt = 0; mt < 4; mt++)
        #pragma unroll
        for (int nt = 0; nt < 4; nt++)
            #pragma unroll
            for (int r = 0; r < 4; r++) acc[mt][nt][r] = 0.0f;

    float4 pa[2], pb[2];
    #pragma unroll
    for (int l = 0; l < 2; l++) {
        pa[l] = *(const float4*)(A + (size_t)(m0 + am[l]) * HID + ak[l]);
        pb[l] = *(const float4*)(B + (size_t)bk[l] * EMB + n0 + bn[l]);
    }
    #pragma unroll
    for (int l = 0; l < 2; l++) {
        sts4_tf32(&As[0][am[l] * ASTR + ak[l]], pa[l]);
        sts4_tf32(&Bs[0][bk[l] * BSTR + bn[l]], pb[l]);
    }
    __syncthreads();

    for (int ks = 0; ks < 64; ks++) {
        int cur = ks & 1;
        if (ks < 63) {
            int k0 = (ks + 1) * 16;
            #pragma unroll
            for (int l = 0; l < 2; l++) {
                pa[l] = *(const float4*)(A + (size_t)(m0 + am[l]) * HID + k0 + ak[l]);
                pb[l] = *(const float4*)(B + (size_t)(k0 + bk[l]) * EMB + n0 + bn[l]);
            }
        }
        #pragma unroll
        for (int k8 = 0; k8 < 2; k8++) {
            int kb = k8 * 8 + 2 * lq;
            float2 av[4][2];
            #pragma unroll
            for (int mt = 0; mt < 4; mt++) {
                int r = wm * 64 + mt * 16 + lr;
                av[mt][0] = *(const float2*)&As[cur][r * ASTR + kb];
                av[mt][1] = *(const float2*)&As[cur][(r + 8) * ASTR + kb];
            }
            float bx[4], by[4];
            #pragma unroll
            for (int nt = 0; nt < 4; nt++) {
                int cc = wn * 32 + nt * 8 + lr;
                bx[nt] = Bs[cur][kb * BSTR + cc];
                by[nt] = Bs[cur][(kb + 1) * BSTR + cc];
            }
            #pragma unroll
            for (int mt = 0; mt < 4; mt++)
                #pragma unroll
                for (int nt = 0; nt < 4; nt++)
                    mma8(acc[mt][nt], av[mt][0], av[mt][1], bx[nt], by[nt]);
        }
        if (ks < 63) {
            #pragma unroll
            for (int l = 0; l < 2; l++) {
                sts4_tf32(&As[cur ^ 1][am[l] * ASTR + ak[l]], pa[l]);
                sts4_tf32(&Bs[cur ^ 1][bk[l] * BSTR + bn[l]], pb[l]);
            }
        }
        __syncthreads();
    }

    #pragma unroll
    for (int mt = 0; mt < 4; mt++) {
        #pragma unroll
        for (int nt = 0; nt < 4; nt++) {
            int row = m0 + wm * 64 + mt * 16 + lr;
            int col = n0 + wn * 32 + nt * 8 + 2 * lq;
            float2 bb = *(const float2*)&bias[col];
            *(float2*)&C[(size_t)row * EMB + col] =
                make_float2(acc[mt][nt][0] + bb.x, acc[mt][nt][1] + bb.y);
            *(float2*)&C[(size_t)(row + 8) * EMB + col] =
                make_float2(acc[mt][nt][2] + bb.x, acc[mt][nt][3] + bb.y);
        }
    }
}

// ---------------- windowed attention (unchanged from R6) ----------------
#define TQ    64
#define SPAN  320
#define SP    328
#define AQP   68
#define RWP   272
#define PPW   272
#define KVP   68
#define OFF_QC 0
#define OFF_QR 4352
#define OFF_RW 8704
#define OFF_SS 4352
#define OFF_PS 26112
#define OFF_KV 43520
#define ATTN_FLOATS 47872

__global__ void __launch_bounds__(256, 1)
attn_mma_kernel(const float* __restrict__ QC, const float* __restrict__ QR,
                const float* __restrict__ K,  const float* __restrict__ V,
                const float* __restrict__ RwinT, float* __restrict__ AO) {
    extern __shared__ float sm[];
    int tid = threadIdx.x;
    int wid = tid >> 5, lane = tid & 31;
    int lr = lane >> 2, lq = lane & 3;
    int wm = wid & 3, wn = wid >> 2;
    int t0 = blockIdx.x * TQ, h = blockIdx.y, b = blockIdx.z;
    size_t bh = (size_t)(b * HEADS + h);
    const float* qcb = QC + (bh << 16) + (size_t)t0 * 64;
    const float* qrb = QR + (bh << 16) + (size_t)t0 * 64;
    const float* kb  = K  + (bh << 16);
    const float* vb  = V  + (bh << 16);
    int j0base = t0 - WIN;

    #pragma unroll
    for (int l = 0; l < 4; l++) {
        int fidx = tid + 256 * l;
        int t = fidx >> 4, d = (fidx & 15) << 2;
        float4 a = *(const float4*)(qcb + t * 64 + d);
        float4 r = *(const float4*)(qrb + t * 64 + d);
        sts4_tf32(&sm[OFF_QC + t * AQP + d], a);
        sts4_tf32(&sm[OFF_QR + t * AQP + d], r);
    }
    for (int idx = tid; idx < 64 * RWP; idx += 256) {
        int d = idx / RWP, u = idx - d * RWP;
        float v = (u < NREL) ? RwinT[d * NREL + u] : 0.0f;
        sm[OFF_RW + d * RWP + u] = to_tf32(v);
    }
    __syncthreads();

    {
        float pc[17][4];
        #pragma unroll
        for (int nt = 0; nt < 17; nt++)
            #pragma unroll
            for (int r = 0; r < 4; r++) pc[nt][r] = 0.0f;
        #pragma unroll
        for (int k8 = 0; k8 < 8; k8++) {
            int kbi = k8 * 8 + 2 * lq;
            int r = wm * 16 + lr;
            float2 alo = *(const float2*)&sm[OFF_QR + r * AQP + kbi];
            float2 ahi = *(const float2*)&sm[OFF_QR + (r + 8) * AQP + kbi];
            #pragma unroll
            for (int nt = 0; nt < 17; nt++) {
                int cc = wn * 136 + nt * 8 + lr;
                float bx = sm[OFF_RW + kbi * RWP + cc];
                float by = sm[OFF_RW + (kbi + 1) * RWP + cc];
                mma8(pc[nt], alo, ahi, bx, by);
            }
        }
        __syncthreads();
        #pragma unroll
        for (int nt = 0; nt < 17; nt++) {
            int cl = wn * 136 + nt * 8 + 2 * lq;
            int m = wm * 16 + lr;
            sm[OFF_PS + m * PPW + cl]           = pc[nt][0];
            sm[OFF_PS + m * PPW + cl + 1]       = pc[nt][1];
            sm[OFF_PS + (m + 8) * PPW + cl]     = pc[nt][2];
            sm[OFF_PS + (m + 8) * PPW + cl + 1] = pc[nt][3];
        }
    }
    __syncthreads();

    for (int c = 0; c < 5; c++) {
        int j0 = j0base + c * 64;
        __syncthreads();
        #pragma unroll
        for (int l = 0; l < 4; l++) {
            int fidx = tid + 256 * l;
            int jl = fidx >> 4, d = (fidx & 15) << 2;
            int jg = j0 + jl;
            float4 v = make_float4(0.f, 0.f, 0.f, 0.f);
            if (jg >= 0 && jg < SEQ) v = *(const float4*)(kb + (size_t)jg * 64 + d);
            sm[OFF_KV + (d + 0) * KVP + jl] = to_tf32(v.x);
            sm[OFF_KV + (d + 1) * KVP + jl] = to_tf32(v.y);
            sm[OFF_KV + (d + 2) * KVP + jl] = to_tf32(v.z);
            sm[OFF_KV + (d + 3) * KVP + jl] = to_tf32(v.w);
        }
        __syncthreads();

        float sc[4][4];
        #pragma unroll
        for (int nt = 0; nt < 4; nt++)
            #pragma unroll
            for (int r = 0; r < 4; r++) sc[nt][r] = 0.0f;
        #pragma unroll
        for (int k8 = 0; k8 < 8; k8++) {
            int kbi = k8 * 8 + 2 * lq;
            int r = wm * 16 + lr;
            float2 alo = *(const float2*)&sm[OFF_QC + r * AQP + kbi];
            float2 ahi = *(const float2*)&sm[OFF_QC + (r + 8) * AQP + kbi];
            #pragma unroll
            for (int nt = 0; nt < 4; nt++) {
                int cc = wn * 32 + nt * 8 + lr;
                float bx = sm[OFF_KV + kbi * KVP + cc];
                float by = sm[OFF_KV + (kbi + 1) * KVP + cc];
                mma8(sc[nt], alo, ahi, bx, by);
            }
        }
        #pragma unroll
        for (int nt = 0; nt < 4; nt++) {
            int cl = wn * 32 + nt * 8 + 2 * lq;
            #pragma unroll
            for (int e = 0; e < 4; e++) {
                int m  = wm * 16 + lr + (e >> 1) * 8;
                int jl = c * 64 + cl + (e & 1);
                int jg = j0base + jl;
                int u  = m - jl + 256;
                float val = -1e30f;
                if (jg >= 0 && jg < SEQ && u >= 0 && u < NREL)
                    val = (sc[nt][e] + sm[OFF_PS + m * PPW + u]) * SCALE;
                sm[OFF_SS + m * SP + jl] = val;
            }
        }
    }
    __syncthreads();

    {
        int w = wid, ln = lane;
        for (int t = w * 8; t < w * 8 + 8; t++) {
            float* row = &sm[OFF_SS + t * SP];
            float m = -1e30f;
            for (int idx = ln; idx < SPAN; idx += 32) m = fmaxf(m, row[idx]);
            #pragma unroll
            for (int o = 16; o > 0; o >>= 1) m = fmaxf(m, __shfl_xor_sync(0xffffffffu, m, o));
            float s = 0.0f;
            for (int idx = ln; idx < SPAN; idx += 32) {
                float e = __expf(row[idx] - m);
                row[idx] = e;
                s += e;
            }
            #pragma unroll
            for (int o = 16; o > 0; o >>= 1) s += __shfl_xor_sync(0xffffffffu, s, o);
            float inv = 1.0f / s;
            for (int idx = ln; idx < SPAN; idx += 32) row[idx] = to_tf32(row[idx] * inv);
        }
    }

    float ao_[4][4];
    #pragma unroll
    for (int nt = 0; nt < 4; nt++)
        #pragma unroll
        for (int r = 0; r < 4; r++) ao_[nt][r] = 0.0f;

    for (int c = 0; c < 5; c++) {
        int j0 = j0base + c * 64;
        __syncthreads();
        #pragma unroll
        for (int l = 0; l < 4; l++) {
            int fidx = tid + 256 * l;
            int jl = fidx >> 4, d = (fidx & 15) << 2;
            int jg = j0 + jl;
            float4 v = make_float4(0.f, 0.f, 0.f, 0.f);
            if (jg >= 0 && jg < SEQ) v = *(const float4*)(vb + (size_t)jg * 64 + d);
            sts4_tf32(&sm[OFF_KV + jl * KVP + d], v);
        }
        __syncthreads();

        #pragma unroll
        for (int k8 = 0; k8 < 8; k8++) {
            int kbi = k8 * 8 + 2 * lq;
            int r = wm * 16 + lr;
            float2 alo = *(const float2*)&sm[OFF_SS + r * SP + c * 64 + kbi];
            float2 ahi = *(const float2*)&sm[OFF_SS + (r + 8) * SP + c * 64 + kbi];
            #pragma unroll
            for (int nt = 0; nt < 4; nt++) {
                int cc = wn * 32 + nt * 8 + lr;
                float bx = sm[OFF_KV + kbi * KVP + cc];
                float by = sm[OFF_KV + (kbi + 1) * KVP + cc];
                mma8(ao_[nt], alo, ahi, bx, by);
            }
        }
    }

    #pragma unroll
    for (int nt = 0; nt < 4; nt++) {
        int n = wn * 32 + nt * 8 + 2 * lq;
        int m = wm * 16 + lr;
        size_t o0 = ((size_t)(b * SEQ + t0 + m)) * HID + h * 64 + n;
        size_t o1 = ((size_t)(b * SEQ + t0 + m + 8)) * HID + h * 64 + n;
        *(float2*)&AO[o0] = make_float2(ao_[nt][0], ao_[nt][1]);
        *(float2*)&AO[o1] = make_float2(ao_[nt][2], ao_[nt][3]);
    }
}

// ---------------- host ----------------
extern "C" void kernel_launch(void* const* d_in, const int* in_sizes, int n_in,
                              void* d_out, int out_size) {
    const float* x    = (const float*)d_in[0];
    const float* Wq   = (const float*)d_in[1];
    const float* Wk   = (const float*)d_in[2];
    const float* Wv   = (const float*)d_in[3];
    const float* cb   = (const float*)d_in[4];
    const float* rb   = (const float*)d_in[5];
    const float* Wrel = (const float*)d_in[6];
    const float* brel = (const float*)d_in[7];
    const float* Wo   = (const float*)d_in[8];
    const float* bo   = (const float*)d_in[9];
    float* out = (float*)d_out;

    float *qc, *qr, *kt, *vt, *ao, *rwint;
    cudaGetSymbolAddress((void**)&qc,    g_qc);
    cudaGetSymbolAddress((void**)&qr,    g_qr);
    cudaGetSymbolAddress((void**)&kt,    g_k);
    cudaGetSymbolAddress((void**)&vt,    g_v);
    cudaGetSymbolAddress((void**)&ao,    g_ao);
    cudaGetSymbolAddress((void**)&rwint, g_rwint);

    rwin_kernel<<<(64 * NREL + 255) / 256, 256>>>(Wrel, brel, rwint);

    // fused QKV: grid 24x32 (which = bx>>3)
    gemm_qkv_tf32<<<dim3(24, 32), 256>>>(x, Wq, Wk, Wv, cb, rb, qc, qr, kt, vt);

    size_t attn_smem = (size_t)ATTN_FLOATS * sizeof(float);
    cudaFuncSetAttribute(attn_mma_kernel, cudaFuncAttributeMaxDynamicSharedMemorySize,
                         (int)attn_smem);
    attn_mma_kernel<<<dim3(SEQ / TQ, HEADS, BATCH), 256, attn_smem>>>(
        qc, qr, kt, vt, rwint, ao);

    gemm_proj_tf32<<<dim3(8, 32), 256>>>(ao, Wo, bo, out);
}

// round 8
// speedup vs baseline: 2.5192x; 1.0760x over previous
#include <cuda_runtime.h>
#include <cuda_bf16.h>
#include <stdint.h>
#include <math.h>

#define BATCH 4
#define SEQ   1024
#define EMB   1024
#define HEADS 16
#define HDIM  64
#define HID   1024
#define WIN   128
#define NREL  257
#define NRELP 272
#define SCALE 0.03125f

// ---------------- scratch (all tf32-rounded at producer) ----------------
__device__ float g_qc[(size_t)BATCH*HEADS*SEQ*HDIM];   // [bh][t][d]
__device__ float g_qr[(size_t)BATCH*HEADS*SEQ*HDIM];   // [bh][t][d]
__device__ float g_k [(size_t)BATCH*HEADS*SEQ*HDIM];   // [bh][t][d]
__device__ float g_v [(size_t)BATCH*HEADS*SEQ*HDIM];   // [bh][d][t]  TRANSPOSED
__device__ float g_ao[(size_t)BATCH*SEQ*HID];          // fp32 [b][t][hid]
__device__ float g_rwin[NRELP*64];                     // [u][d], u padded to 272, tf32

__device__ __forceinline__ float to_tf32(float x) {
    unsigned int r;
    asm("cvt.rna.tf32.f32 %0, %1;" : "=r"(r) : "f"(x));
    return __uint_as_float(r);
}

// ---------------- Rwin precompute: [u][d], tf32, zero-padded u>=257 --------
__global__ void rwin_kernel(const float* __restrict__ W_rel,
                            const float* __restrict__ b_rel,
                            float* __restrict__ Rwin) {
    int gid = blockIdx.x * blockDim.x + threadIdx.x;
    if (gid >= NRELP * 64) return;
    int d = gid & 63;
    int u = gid >> 6;
    float out = 0.0f;
    if (u < NREL) {
        float pos = (float)(u - WIN);
        float s = b_rel[d];
        #pragma unroll 8
        for (int f = 0; f < 32; f++) {
            float inv = powf(10000.0f, -(2.0f * (float)f) / 64.0f);
            float a = pos * inv;
            s += sinf(a) * W_rel[f * 64 + d];
            s += cosf(a) * W_rel[(f + 32) * 64 + d];
        }
        out = to_tf32(s);
    }
    Rwin[u * 64 + d] = out;
}

// ---------------- mma primitive ----------------
__device__ __forceinline__ void mma8(float c[4], float2 alo, float2 ahi, float b0, float b1) {
    asm volatile(
        "mma.sync.aligned.m16n8k8.row.col.f32.tf32.tf32.f32 "
        "{%0,%1,%2,%3}, {%4,%5,%6,%7}, {%8,%9}, {%0,%1,%2,%3};"
        : "+f"(c[0]), "+f"(c[1]), "+f"(c[2]), "+f"(c[3])
        : "r"(__float_as_uint(alo.x)), "r"(__float_as_uint(ahi.x)),
          "r"(__float_as_uint(alo.y)), "r"(__float_as_uint(ahi.y)),
          "r"(__float_as_uint(b0)),   "r"(__float_as_uint(b1)));
}

#define ASTR 18
#define BSTR 132

__device__ __forceinline__ void sts4_tf32(float* p, float4 v) {
    p[0] = to_tf32(v.x); p[1] = to_tf32(v.y);
    p[2] = to_tf32(v.z); p[3] = to_tf32(v.w);
}

// ---------------- fused QKV GEMM, double-buffered (epilogue stores tf32) ---
__global__ void __launch_bounds__(256, 2)
gemm_qkv_tf32(const float* __restrict__ X,
              const float* __restrict__ Wq, const float* __restrict__ Wk,
              const float* __restrict__ Wv,
              const float* __restrict__ cb, const float* __restrict__ rb,
              float* __restrict__ qc, float* __restrict__ qr,
              float* __restrict__ kt, float* __restrict__ vt) {
    __shared__ float As[2][128 * ASTR];
    __shared__ float Bs[2][16 * BSTR];

    int tid = threadIdx.x;
    int wid = tid >> 5, lane = tid & 31;
    int lr = lane >> 2, lq = lane & 3;
    int wm = wid & 1, wn = wid >> 1;
    int which = blockIdx.x >> 3;
    const float* B = (which == 0) ? Wq : ((which == 1) ? Wk : Wv);
    int n0 = (blockIdx.x & 7) * 128;
    int m0 = blockIdx.y * 128;

    int am[2], ak[2], bk[2], bn[2];
    #pragma unroll
    for (int l = 0; l < 2; l++) {
        int fidx = tid + 256 * l;
        am[l] = fidx >> 2;  ak[l] = (fidx & 3) << 2;
        bk[l] = fidx >> 5;  bn[l] = (fidx & 31) << 2;
    }

    float acc[4][4][4];
    #pragma unroll
    for (int mt = 0; mt < 4; mt++)
        #pragma unroll
        for (int nt = 0; nt < 4; nt++)
            #pragma unroll
            for (int r = 0; r < 4; r++) acc[mt][nt][r] = 0.0f;

    float4 pa[2], pb[2];
    #pragma unroll
    for (int l = 0; l < 2; l++) {
        pa[l] = *(const float4*)(X + (size_t)(m0 + am[l]) * EMB + ak[l]);
        pb[l] = *(const float4*)(B + (size_t)bk[l] * HID + n0 + bn[l]);
    }
    #pragma unroll
    for (int l = 0; l < 2; l++) {
        sts4_tf32(&As[0][am[l] * ASTR + ak[l]], pa[l]);
        sts4_tf32(&Bs[0][bk[l] * BSTR + bn[l]], pb[l]);
    }
    __syncthreads();

    for (int ks = 0; ks < 64; ks++) {
        int cur = ks & 1;
        if (ks < 63) {
            int k0 = (ks + 1) * 16;
            #pragma unroll
            for (int l = 0; l < 2; l++) {
                pa[l] = *(const float4*)(X + (size_t)(m0 + am[l]) * EMB + k0 + ak[l]);
                pb[l] = *(const float4*)(B + (size_t)(k0 + bk[l]) * HID + n0 + bn[l]);
            }
        }
        #pragma unroll
        for (int k8 = 0; k8 < 2; k8++) {
            int kb = k8 * 8 + 2 * lq;
            float2 av[4][2];
            #pragma unroll
            for (int mt = 0; mt < 4; mt++) {
                int r = wm * 64 + mt * 16 + lr;
                av[mt][0] = *(const float2*)&As[cur][r * ASTR + kb];
                av[mt][1] = *(const float2*)&As[cur][(r + 8) * ASTR + kb];
            }
            float bx[4], by[4];
            #pragma unroll
            for (int nt = 0; nt < 4; nt++) {
                int cc = wn * 32 + nt * 8 + lr;
                bx[nt] = Bs[cur][kb * BSTR + cc];
                by[nt] = Bs[cur][(kb + 1) * BSTR + cc];
            }
            #pragma unroll
            for (int mt = 0; mt < 4; mt++)
                #pragma unroll
                for (int nt = 0; nt < 4; nt++)
                    mma8(acc[mt][nt], av[mt][0], av[mt][1], bx[nt], by[nt]);
        }
        if (ks < 63) {
            #pragma unroll
            for (int l = 0; l < 2; l++) {
                sts4_tf32(&As[cur ^ 1][am[l] * ASTR + ak[l]], pa[l]);
                sts4_tf32(&Bs[cur ^ 1][bk[l] * BSTR + bn[l]], pb[l]);
            }
        }
        __syncthreads();
    }

    #pragma unroll
    for (int mt = 0; mt < 4; mt++) {
        #pragma unroll
        for (int nt = 0; nt < 4; nt++) {
            int row = m0 + wm * 64 + mt * 16 + lr;
            int col = n0 + wn * 32 + nt * 8 + 2 * lq;
            float c0 = acc[mt][nt][0], c1 = acc[mt][nt][1];
            float c2 = acc[mt][nt][2], c3 = acc[mt][nt][3];
            int b = row >> 10, t = row & 1023;
            int hh = col >> 6, dd = col & 63;
            size_t base = (((size_t)(b * HEADS + hh)) << 16);
            if (which == 0) {
                float2 cbv = *(const float2*)&cb[col];
                float2 rbv = *(const float2*)&rb[col];
                *(float2*)&qc[base + (size_t)t * 64 + dd] =
                    make_float2(to_tf32(c0 + cbv.x), to_tf32(c1 + cbv.y));
                *(float2*)&qc[base + (size_t)(t + 8) * 64 + dd] =
                    make_float2(to_tf32(c2 + cbv.x), to_tf32(c3 + cbv.y));
                *(float2*)&qr[base + (size_t)t * 64 + dd] =
                    make_float2(to_tf32(c0 + rbv.x), to_tf32(c1 + rbv.y));
                *(float2*)&qr[base + (size_t)(t + 8) * 64 + dd] =
                    make_float2(to_tf32(c2 + rbv.x), to_tf32(c3 + rbv.y));
            } else if (which == 1) {
                *(float2*)&kt[base + (size_t)t * 64 + dd] =
                    make_float2(to_tf32(c0), to_tf32(c1));
                *(float2*)&kt[base + (size_t)(t + 8) * 64 + dd] =
                    make_float2(to_tf32(c2), to_tf32(c3));
            } else {
                // transposed [bh][d][t]
                vt[base + (size_t)dd * 1024 + t]           = to_tf32(c0);
                vt[base + (size_t)(dd + 1) * 1024 + t]     = to_tf32(c1);
                vt[base + (size_t)dd * 1024 + t + 8]       = to_tf32(c2);
                vt[base + (size_t)(dd + 1) * 1024 + t + 8] = to_tf32(c3);
            }
        }
    }
}

// ---------------- out-proj GEMM (unchanged) ----------------
__global__ void __launch_bounds__(256, 2)
gemm_proj_tf32(const float* __restrict__ A, const float* __restrict__ B,
               const float* __restrict__ bias, float* __restrict__ C) {
    __shared__ float As[2][128 * ASTR];
    __shared__ float Bs[2][16 * BSTR];

    int tid = threadIdx.x;
    int wid = tid >> 5, lane = tid & 31;
    int lr = lane >> 2, lq = lane & 3;
    int wm = wid & 1, wn = wid >> 1;
    int n0 = blockIdx.x * 128, m0 = blockIdx.y * 128;

    int am[2], ak[2], bk[2], bn[2];
    #pragma unroll
    for (int l = 0; l < 2; l++) {
        int fidx = tid + 256 * l;
        am[l] = fidx >> 2;  ak[l] = (fidx & 3) << 2;
        bk[l] = fidx >> 5;  bn[l] = (fidx & 31) << 2;
    }

    float acc[4][4][4];
    #pragma unroll
    for (int mt = 0; mt < 4; mt++)
        #pragma unroll
        for (int nt = 0; nt < 4; nt++)
            #pragma unroll
            for (int r = 0; r < 4; r++) acc[mt][nt][r] = 0.0f;

    float4 pa[2], pb[2];
    #pragma unroll
    for (int l = 0; l < 2; l++) {
        pa[l] = *(const float4*)(A + (size_t)(m0 + am[l]) * HID + ak[l]);
        pb[l] = *(const float4*)(B + (size_t)bk[l] * EMB + n0 + bn[l]);
    }
    #pragma unroll
    for (int l = 0; l < 2; l++) {
        sts4_tf32(&As[0][am[l] * ASTR + ak[l]], pa[l]);
        sts4_tf32(&Bs[0][bk[l] * BSTR + bn[l]], pb[l]);
    }
    __syncthreads();

    for (int ks = 0; ks < 64; ks++) {
        int cur = ks & 1;
        if (ks < 63) {
            int k0 = (ks + 1) * 16;
            #pragma unroll
            for (int l = 0; l < 2; l++) {
                pa[l] = *(const float4*)(A + (size_t)(m0 + am[l]) * HID + k0 + ak[l]);
                pb[l] = *(const float4*)(B + (size_t)(k0 + bk[l]) * EMB + n0 + bn[l]);
            }
        }
        #pragma unroll
        for (int k8 = 0; k8 < 2; k8++) {
            int kb = k8 * 8 + 2 * lq;
            float2 av[4][2];
            #pragma unroll
            for (int mt = 0; mt < 4; mt++) {
                int r = wm * 64 + mt * 16 + lr;
                av[mt][0] = *(const float2*)&As[cur][r * ASTR + kb];
                av[mt][1] = *(const float2*)&As[cur][(r + 8) * ASTR + kb];
            }
            float bx[4], by[4];
            #pragma unroll
            for (int nt = 0; nt < 4; nt++) {
                int cc = wn * 32 + nt * 8 + lr;
                bx[nt] = Bs[cur][kb * BSTR + cc];
                by[nt] = Bs[cur][(kb + 1) * BSTR + cc];
            }
            #pragma unroll
            for (int mt = 0; mt < 4; mt++)
                #pragma unroll
                for (int nt = 0; nt < 4; nt++)
                    mma8(acc[mt][nt], av[mt][0], av[mt][1], bx[nt], by[nt]);
        }
        if (ks < 63) {
            #pragma unroll
            for (int l = 0; l < 2; l++) {
                sts4_tf32(&As[cur ^ 1][am[l] * ASTR + ak[l]], pa[l]);
                sts4_tf32(&Bs[cur ^ 1][bk[l] * BSTR + bn[l]], pb[l]);
            }
        }
        __syncthreads();
    }

    #pragma unroll
    for (int mt = 0; mt < 4; mt++) {
        #pragma unroll
        for (int nt = 0; nt < 4; nt++) {
            int row = m0 + wm * 64 + mt * 16 + lr;
            int col = n0 + wn * 32 + nt * 8 + 2 * lq;
            float2 bb = *(const float2*)&bias[col];
            *(float2*)&C[(size_t)row * EMB + col] =
                make_float2(acc[mt][nt][0] + bb.x, acc[mt][nt][1] + bb.y);
            *(float2*)&C[(size_t)(row + 8) * EMB + col] =
                make_float2(acc[mt][nt][2] + bb.x, acc[mt][nt][3] + bb.y);
        }
    }
}

// ---------------- windowed attention: operand-native layouts ----------------
#define TQ    64
#define SPAN  320
#define SP    328
#define AQP   68    // Qc/Qr [t][d]
#define RWP   68    // Rwin [u][d]
#define PPW   272   // Prel [m][u]
#define KVP   68    // K [j][d] / V [d][j]
#define KVSZ  4352
#define OFF_QC 0
#define OFF_QR 4352
#define OFF_RW 8704                      // 272*68 = 18496 -> ends 27200
#define OFF_SS 4352                      // overlays QR+RW (needs 20992 <= 22848)
#define OFF_PS 27200                     // 17408 -> ends 44608
#define OFF_KV 44608                     // 2*4352 -> ends 53312
#define ATTN_FLOATS 53312                // 213248 B

__global__ void __launch_bounds__(256, 1)
attn_mma_kernel(const float* __restrict__ QC, const float* __restrict__ QR,
                const float* __restrict__ K,  const float* __restrict__ Vt,
                const float* __restrict__ RW, float* __restrict__ AO) {
    extern __shared__ float sm[];
    int tid = threadIdx.x;
    int wid = tid >> 5, lane = tid & 31;
    int lr = lane >> 2, lq = lane & 3;
    int wm = wid & 3, wn = wid >> 2;
    int t0 = blockIdx.x * TQ, h = blockIdx.y, b = blockIdx.z;
    size_t bh = (size_t)(b * HEADS + h);
    const float* qcb = QC + (bh << 16) + (size_t)t0 * 64;
    const float* qrb = QR + (bh << 16) + (size_t)t0 * 64;
    const float* kb  = K  + (bh << 16);
    const float* vb  = Vt + (bh << 16);
    int j0base = t0 - WIN;

    // ---- load Q tiles (pre-rounded tf32, straight float4) ----
    #pragma unroll
    for (int l = 0; l < 4; l++) {
        int fidx = tid + 256 * l;
        int t = fidx >> 4, d = (fidx & 15) << 2;
        *(float4*)&sm[OFF_QC + t * AQP + d] = *(const float4*)(qcb + t * 64 + d);
        *(float4*)&sm[OFF_QR + t * AQP + d] = *(const float4*)(qrb + t * 64 + d);
    }
    // ---- load Rwin [u][d]: 17 float4 per thread ----
    #pragma unroll 4
    for (int l = 0; l < 17; l++) {
        int fidx = tid + 256 * l;
        int u = fidx >> 4, d = (fidx & 15) << 2;
        *(float4*)&sm[OFF_RW + u * RWP + d] = *(const float4*)(RW + u * 64 + d);
    }
    __syncthreads();

    // ---- Prel = Qr @ Rwin^T ; B-frag = float2 from [u][d] ----
    {
        float pc[17][4];
        #pragma unroll
        for (int nt = 0; nt < 17; nt++)
            #pragma unroll
            for (int r = 0; r < 4; r++) pc[nt][r] = 0.0f;
        #pragma unroll
        for (int k8 = 0; k8 < 8; k8++) {
            int kbi = k8 * 8 + 2 * lq;
            int r = wm * 16 + lr;
            float2 alo = *(const float2*)&sm[OFF_QR + r * AQP + kbi];
            float2 ahi = *(const float2*)&sm[OFF_QR + (r + 8) * AQP + kbi];
            #pragma unroll
            for (int nt = 0; nt < 17; nt++) {
                int cc = wn * 136 + nt * 8 + lr;
                float2 bv = *(const float2*)&sm[OFF_RW + cc * RWP + kbi];
                mma8(pc[nt], alo, ahi, bv.x, bv.y);
            }
        }
        #pragma unroll
        for (int nt = 0; nt < 17; nt++) {
            int cl = wn * 136 + nt * 8 + 2 * lq;
            int m = wm * 16 + lr;
            *(float2*)&sm[OFF_PS + m * PPW + cl]       = make_float2(pc[nt][0], pc[nt][1]);
            *(float2*)&sm[OFF_PS + (m + 8) * PPW + cl] = make_float2(pc[nt][2], pc[nt][3]);
        }
    }
    __syncthreads();   // Prel done; QR/RW become SS

    // ---- scores: S = Qc @ K^T + gather(Prel); K double-buffered ----
    {
        int j0 = j0base;
        if (j0 > -64) {   // chunk 0 live? (j0 < SEQ always for c=0)
            #pragma unroll
            for (int l = 0; l < 4; l++) {
                int fidx = tid + 256 * l;
                int jl = fidx >> 4, d = (fidx & 15) << 2;
                int jg = j0 + jl;
                float4 v = make_float4(0.f, 0.f, 0.f, 0.f);
                if (jg >= 0 && jg < SEQ) v = *(const float4*)(kb + (size_t)jg * 64 + d);
                *(float4*)&sm[OFF_KV + jl * KVP + d] = v;
            }
        }
    }
    __syncthreads();

    for (int c = 0; c < 5; c++) {
        int cur = c & 1;
        int j0 = j0base + c * 64;
        bool live = (j0 > -64) && (j0 < SEQ);

        float4 pk[4];
        bool liven = false;
        if (c < 4) {
            int j0n = j0base + (c + 1) * 64;
            liven = (j0n > -64) && (j0n < SEQ);
            if (liven) {
                #pragma unroll
                for (int l = 0; l < 4; l++) {
                    int fidx = tid + 256 * l;
                    int jl = fidx >> 4, d = (fidx & 15) << 2;
                    int jg = j0n + jl;
                    pk[l] = make_float4(0.f, 0.f, 0.f, 0.f);
                    if (jg >= 0 && jg < SEQ) pk[l] = *(const float4*)(kb + (size_t)jg * 64 + d);
                }
            }
        }

        if (live) {
            float sc[4][4];
            #pragma unroll
            for (int nt = 0; nt < 4; nt++)
                #pragma unroll
                for (int r = 0; r < 4; r++) sc[nt][r] = 0.0f;
            #pragma unroll
            for (int k8 = 0; k8 < 8; k8++) {
                int kbi = k8 * 8 + 2 * lq;
                int r = wm * 16 + lr;
                float2 alo = *(const float2*)&sm[OFF_QC + r * AQP + kbi];
                float2 ahi = *(const float2*)&sm[OFF_QC + (r + 8) * AQP + kbi];
                #pragma unroll
                for (int nt = 0; nt < 4; nt++) {
                    int cc = wn * 32 + nt * 8 + lr;
                    float2 bv = *(const float2*)&sm[OFF_KV + cur * KVSZ + cc * KVP + kbi];
                    mma8(sc[nt], alo, ahi, bv.x, bv.y);
                }
            }
            #pragma unroll
            for (int nt = 0; nt < 4; nt++) {
                int cl = wn * 32 + nt * 8 + 2 * lq;
                #pragma unroll
                for (int e = 0; e < 4; e++) {
                    int m  = wm * 16 + lr + (e >> 1) * 8;
                    int jl = c * 64 + cl + (e & 1);
                    int jg = j0base + jl;
                    int u  = m - jl + 256;
                    float val = -1e30f;
                    if (jg >= 0 && jg < SEQ && u >= 0 && u < NREL)
                        val = (sc[nt][e] + sm[OFF_PS + m * PPW + u]) * SCALE;
                    sm[OFF_SS + m * SP + jl] = val;
                }
            }
        } else {
            #pragma unroll
            for (int nt = 0; nt < 4; nt++) {
                int cl = wn * 32 + nt * 8 + 2 * lq;
                #pragma unroll
                for (int e = 0; e < 4; e++) {
                    int m  = wm * 16 + lr + (e >> 1) * 8;
                    int jl = c * 64 + cl + (e & 1);
                    sm[OFF_SS + m * SP + jl] = -1e30f;
                }
            }
        }

        if (c < 4) {
            if (liven) {
                #pragma unroll
                for (int l = 0; l < 4; l++) {
                    int fidx = tid + 256 * l;
                    int jl = fidx >> 4, d = (fidx & 15) << 2;
                    *(float4*)&sm[OFF_KV + (cur ^ 1) * KVSZ + jl * KVP + d] = pk[l];
                }
            }
            __syncthreads();
        }
    }
    __syncthreads();

    // ---- softmax, float4 sweeps (row = 320 = 80 float4) ----
    {
        for (int t = wid * 8; t < wid * 8 + 8; t++) {
            float4* row = (float4*)&sm[OFF_SS + t * SP];
            float m = -1e30f;
            for (int i = lane; i < 80; i += 32) {
                float4 v = row[i];
                m = fmaxf(m, fmaxf(fmaxf(v.x, v.y), fmaxf(v.z, v.w)));
            }
            #pragma unroll
            for (int o = 16; o > 0; o >>= 1) m = fmaxf(m, __shfl_xor_sync(0xffffffffu, m, o));
            float s = 0.0f;
            for (int i = lane; i < 80; i += 32) {
                float4 v = row[i];
                v.x = __expf(v.x - m); v.y = __expf(v.y - m);
                v.z = __expf(v.z - m); v.w = __expf(v.w - m);
                s += v.x + v.y + v.z + v.w;
                row[i] = v;
            }
            #pragma unroll
            for (int o = 16; o > 0; o >>= 1) s += __shfl_xor_sync(0xffffffffu, s, o);
            float inv = 1.0f / s;
            for (int i = lane; i < 80; i += 32) {
                float4 v = row[i];
                v.x = to_tf32(v.x * inv); v.y = to_tf32(v.y * inv);
                v.z = to_tf32(v.z * inv); v.w = to_tf32(v.w * inv);
                row[i] = v;
            }
        }
    }
    __syncthreads();

    // ---- O = P @ V; V smem [d][j], double-buffered ----
    float ao_[4][4];
    #pragma unroll
    for (int nt = 0; nt < 4; nt++)
        #pragma unroll
        for (int r = 0; r < 4; r++) ao_[nt][r] = 0.0f;

    {
        int j0 = j0base;
        if (j0 > -64) {
            #pragma unroll
            for (int l = 0; l < 4; l++) {
                int fidx = tid + 256 * l;
                int dd = fidx >> 4, jl4 = (fidx & 15) << 2;
                int jg = j0 + jl4;
                float4 v;
                if (j0 >= 0 && j0 + 63 < SEQ) {
                    v = *(const float4*)(vb + (size_t)dd * 1024 + jg);
                } else {
                    v.x = (jg     >= 0 && jg     < SEQ) ? vb[(size_t)dd * 1024 + jg]     : 0.f;
                    v.y = (jg + 1 >= 0 && jg + 1 < SEQ) ? vb[(size_t)dd * 1024 + jg + 1] : 0.f;
                    v.z = (jg + 2 >= 0 && jg + 2 < SEQ) ? vb[(size_t)dd * 1024 + jg + 2] : 0.f;
                    v.w = (jg + 3 >= 0 && jg + 3 < SEQ) ? vb[(size_t)dd * 1024 + jg + 3] : 0.f;
                }
                *(float4*)&sm[OFF_KV + dd * KVP + jl4] = v;
            }
        }
    }
    __syncthreads();

    for (int c = 0; c < 5; c++) {
        int cur = c & 1;
        int j0 = j0base + c * 64;
        bool live = (j0 > -64) && (j0 < SEQ);

        float4 pk[4];
        bool liven = false;
        if (c < 4) {
            int j0n = j0base + (c + 1) * 64;
            liven = (j0n > -64) && (j0n < SEQ);
            if (liven) {
                #pragma unroll
                for (int l = 0; l < 4; l++) {
                    int fidx = tid + 256 * l;
                    int dd = fidx >> 4, jl4 = (fidx & 15) << 2;
                    int jg = j0n + jl4;
                    if (j0n >= 0 && j0n + 63 < SEQ) {
                        pk[l] = *(const float4*)(vb + (size_t)dd * 1024 + jg);
                    } else {
                        pk[l].x = (jg     >= 0 && jg     < SEQ) ? vb[(size_t)dd * 1024 + jg]     : 0.f;
                        pk[l].y = (jg + 1 >= 0 && jg + 1 < SEQ) ? vb[(size_t)dd * 1024 + jg + 1] : 0.f;
                        pk[l].z = (jg + 2 >= 0 && jg + 2 < SEQ) ? vb[(size_t)dd * 1024 + jg + 2] : 0.f;
                        pk[l].w = (jg + 3 >= 0 && jg + 3 < SEQ) ? vb[(size_t)dd * 1024 + jg + 3] : 0.f;
                    }
                }
            }
        }

        if (live) {
            #pragma unroll
            for (int k8 = 0; k8 < 8; k8++) {
                int kbi = k8 * 8 + 2 * lq;
                int r = wm * 16 + lr;
                float2 alo = *(const float2*)&sm[OFF_SS + r * SP + c * 64 + kbi];
                float2 ahi = *(const float2*)&sm[OFF_SS + (r + 8) * SP + c * 64 + kbi];
                #pragma unroll
                for (int nt = 0; nt < 4; nt++) {
                    int cc = wn * 32 + nt * 8 + lr;
                    float2 bv = *(const float2*)&sm[OFF_KV + cur * KVSZ + cc * KVP + kbi];
                    mma8(ao_[nt], alo, ahi, bv.x, bv.y);
                }
            }
        }

        if (c < 4) {
            if (liven) {
                #pragma unroll
                for (int l = 0; l < 4; l++) {
                    int fidx = tid + 256 * l;
                    int dd = fidx >> 4, jl4 = (fidx & 15) << 2;
                    *(float4*)&sm[OFF_KV + (cur ^ 1) * KVSZ + dd * KVP + jl4] = pk[l];
                }
            }
            __syncthreads();
        }
    }

    // ---- write AO ----
    #pragma unroll
    for (int nt = 0; nt < 4; nt++) {
        int n = wn * 32 + nt * 8 + 2 * lq;
        int m = wm * 16 + lr;
        size_t o0 = ((size_t)(b * SEQ + t0 + m)) * HID + h * 64 + n;
        size_t o1 = ((size_t)(b * SEQ + t0 + m + 8)) * HID + h * 64 + n;
        *(float2*)&AO[o0] = make_float2(ao_[nt][0], ao_[nt][1]);
        *(float2*)&AO[o1] = make_float2(ao_[nt][2], ao_[nt][3]);
    }
}

// ---------------- host ----------------
extern "C" void kernel_launch(void* const* d_in, const int* in_sizes, int n_in,
                              void* d_out, int out_size) {
    const float* x    = (const float*)d_in[0];
    const float* Wq   = (const float*)d_in[1];
    const float* Wk   = (const float*)d_in[2];
    const float* Wv   = (const float*)d_in[3];
    const float* cb   = (const float*)d_in[4];
    const float* rb   = (const float*)d_in[5];
    const float* Wrel = (const float*)d_in[6];
    const float* brel = (const float*)d_in[7];
    const float* Wo   = (const float*)d_in[8];
    const float* bo   = (const float*)d_in[9];
    float* out = (float*)d_out;

    float *qc, *qr, *kt, *vt, *ao, *rwin;
    cudaGetSymbolAddress((void**)&qc,   g_qc);
    cudaGetSymbolAddress((void**)&qr,   g_qr);
    cudaGetSymbolAddress((void**)&kt,   g_k);
    cudaGetSymbolAddress((void**)&vt,   g_v);
    cudaGetSymbolAddress((void**)&ao,   g_ao);
    cudaGetSymbolAddress((void**)&rwin, g_rwin);

    rwin_kernel<<<(NRELP * 64 + 255) / 256, 256>>>(Wrel, brel, rwin);

    gemm_qkv_tf32<<<dim3(24, 32), 256>>>(x, Wq, Wk, Wv, cb, rb, qc, qr, kt, vt);

    size_t attn_smem = (size_t)ATTN_FLOATS * sizeof(float);
    cudaFuncSetAttribute(attn_mma_kernel, cudaFuncAttributeMaxDynamicSharedMemorySize,
                         (int)attn_smem);
    attn_mma_kernel<<<dim3(SEQ / TQ, HEADS, BATCH), 256, attn_smem>>>(
        qc, qr, kt, vt, rwin, ao);

    gemm_proj_tf32<<<dim3(8, 32), 256>>>(ao, Wo, bo, out);
}

// round 9
// speedup vs baseline: 2.6000x; 1.0321x over previous
#include <cuda_runtime.h>
#include <cuda_bf16.h>
#include <stdint.h>
#include <math.h>

#define BATCH 4
#define SEQ   1024
#define EMB   1024
#define HEADS 16
#define HDIM  64
#define HID   1024
#define WIN   128
#define NREL  257
#define NRELP 272
#define SCALE 0.03125f

// ---------------- scratch (all tf32-rounded at producer) ----------------
__device__ float g_qc[(size_t)BATCH*HEADS*SEQ*HDIM];   // [bh][t][d]
__device__ float g_qr[(size_t)BATCH*HEADS*SEQ*HDIM];   // [bh][t][d]
__device__ float g_k [(size_t)BATCH*HEADS*SEQ*HDIM];   // [bh][t][d]
__device__ float g_v [(size_t)BATCH*HEADS*SEQ*HDIM];   // [bh][d][t]  TRANSPOSED
__device__ float g_ao[(size_t)BATCH*SEQ*HID];          // fp32 [b][t][hid]
__device__ float g_rwin[NRELP*64];                     // [u][d], tf32

__device__ __forceinline__ float to_tf32(float x) {
    unsigned int r;
    asm("cvt.rna.tf32.f32 %0, %1;" : "=r"(r) : "f"(x));
    return __uint_as_float(r);
}

// ---------------- Rwin precompute ----------------
__global__ void rwin_kernel(const float* __restrict__ W_rel,
                            const float* __restrict__ b_rel,
                            float* __restrict__ Rwin) {
    int gid = blockIdx.x * blockDim.x + threadIdx.x;
    if (gid >= NRELP * 64) return;
    int d = gid & 63;
    int u = gid >> 6;
    float out = 0.0f;
    if (u < NREL) {
        float pos = (float)(u - WIN);
        float s = b_rel[d];
        #pragma unroll 8
        for (int f = 0; f < 32; f++) {
            float inv = powf(10000.0f, -(2.0f * (float)f) / 64.0f);
            float a = pos * inv;
            s += sinf(a) * W_rel[f * 64 + d];
            s += cosf(a) * W_rel[(f + 32) * 64 + d];
        }
        out = to_tf32(s);
    }
    Rwin[u * 64 + d] = out;
}

// ---------------- mma primitive ----------------
__device__ __forceinline__ void mma8(float c[4], float2 alo, float2 ahi, float b0, float b1) {
    asm volatile(
        "mma.sync.aligned.m16n8k8.row.col.f32.tf32.tf32.f32 "
        "{%0,%1,%2,%3}, {%4,%5,%6,%7}, {%8,%9}, {%0,%1,%2,%3};"
        : "+f"(c[0]), "+f"(c[1]), "+f"(c[2]), "+f"(c[3])
        : "r"(__float_as_uint(alo.x)), "r"(__float_as_uint(ahi.x)),
          "r"(__float_as_uint(alo.y)), "r"(__float_as_uint(ahi.y)),
          "r"(__float_as_uint(b0)),   "r"(__float_as_uint(b1)));
}

#define ASTR 18
#define BSTR 132

__device__ __forceinline__ void sts4_tf32(float* p, float4 v) {
    p[0] = to_tf32(v.x); p[1] = to_tf32(v.y);
    p[2] = to_tf32(v.z); p[3] = to_tf32(v.w);
}

// ============ 128x128 block, 4 warps (128 thr), 64x64 warp tiles ============
// Shared GEMM mainloop body via macro-free duplication (two kernels).

// ---------------- fused QKV GEMM ----------------
__global__ void __launch_bounds__(128, 2)
gemm_qkv_tf32(const float* __restrict__ X,
              const float* __restrict__ Wq, const float* __restrict__ Wk,
              const float* __restrict__ Wv,
              const float* __restrict__ cb, const float* __restrict__ rb,
              float* __restrict__ qc, float* __restrict__ qr,
              float* __restrict__ kt, float* __restrict__ vt) {
    __shared__ float As[2][128 * ASTR];
    __shared__ float Bs[2][16 * BSTR];

    int tid = threadIdx.x;
    int wid = tid >> 5, lane = tid & 31;
    int lr = lane >> 2, lq = lane & 3;
    int wm = wid & 1, wn = wid >> 1;          // 2x2 warp grid, 64x64 tiles
    int which = blockIdx.x >> 3;
    const float* B = (which == 0) ? Wq : ((which == 1) ? Wk : Wv);
    int n0 = (blockIdx.x & 7) * 128;
    int m0 = blockIdx.y * 128;

    int am[4], ak[4], bk[4], bn[4];
    #pragma unroll
    for (int l = 0; l < 4; l++) {
        int fidx = tid + 128 * l;
        am[l] = fidx >> 2;  ak[l] = (fidx & 3) << 2;
        bk[l] = fidx >> 5;  bn[l] = (fidx & 31) << 2;
    }

    float acc[4][8][4];
    #pragma unroll
    for (int mt = 0; mt < 4; mt++)
        #pragma unroll
        for (int nt = 0; nt < 8; nt++)
            #pragma unroll
            for (int r = 0; r < 4; r++) acc[mt][nt][r] = 0.0f;

    float4 pa[4], pb[4];
    #pragma unroll
    for (int l = 0; l < 4; l++) {
        pa[l] = *(const float4*)(X + (size_t)(m0 + am[l]) * EMB + ak[l]);
        pb[l] = *(const float4*)(B + (size_t)bk[l] * HID + n0 + bn[l]);
    }
    #pragma unroll
    for (int l = 0; l < 4; l++) {
        sts4_tf32(&As[0][am[l] * ASTR + ak[l]], pa[l]);
        sts4_tf32(&Bs[0][bk[l] * BSTR + bn[l]], pb[l]);
    }
    __syncthreads();

    for (int ks = 0; ks < 64; ks++) {
        int cur = ks & 1;
        if (ks < 63) {
            int k0 = (ks + 1) * 16;
            #pragma unroll
            for (int l = 0; l < 4; l++) {
                pa[l] = *(const float4*)(X + (size_t)(m0 + am[l]) * EMB + k0 + ak[l]);
                pb[l] = *(const float4*)(B + (size_t)(k0 + bk[l]) * HID + n0 + bn[l]);
            }
        }
        #pragma unroll
        for (int k8 = 0; k8 < 2; k8++) {
            int kb = k8 * 8 + 2 * lq;
            float2 av[4][2];
            #pragma unroll
            for (int mt = 0; mt < 4; mt++) {
                int r = wm * 64 + mt * 16 + lr;
                av[mt][0] = *(const float2*)&As[cur][r * ASTR + kb];
                av[mt][1] = *(const float2*)&As[cur][(r + 8) * ASTR + kb];
            }
            #pragma unroll
            for (int nt = 0; nt < 8; nt++) {
                int cc = wn * 64 + nt * 8 + lr;
                float bx = Bs[cur][kb * BSTR + cc];
                float by = Bs[cur][(kb + 1) * BSTR + cc];
                #pragma unroll
                for (int mt = 0; mt < 4; mt++)
                    mma8(acc[mt][nt], av[mt][0], av[mt][1], bx, by);
            }
        }
        if (ks < 63) {
            #pragma unroll
            for (int l = 0; l < 4; l++) {
                sts4_tf32(&As[cur ^ 1][am[l] * ASTR + ak[l]], pa[l]);
                sts4_tf32(&Bs[cur ^ 1][bk[l] * BSTR + bn[l]], pb[l]);
            }
        }
        __syncthreads();
    }

    #pragma unroll
    for (int mt = 0; mt < 4; mt++) {
        #pragma unroll
        for (int nt = 0; nt < 8; nt++) {
            int row = m0 + wm * 64 + mt * 16 + lr;
            int col = n0 + wn * 64 + nt * 8 + 2 * lq;
            float c0 = acc[mt][nt][0], c1 = acc[mt][nt][1];
            float c2 = acc[mt][nt][2], c3 = acc[mt][nt][3];
            int b = row >> 10, t = row & 1023;
            int hh = col >> 6, dd = col & 63;
            size_t base = (((size_t)(b * HEADS + hh)) << 16);
            if (which == 0) {
                float2 cbv = *(const float2*)&cb[col];
                float2 rbv = *(const float2*)&rb[col];
                *(float2*)&qc[base + (size_t)t * 64 + dd] =
                    make_float2(to_tf32(c0 + cbv.x), to_tf32(c1 + cbv.y));
                *(float2*)&qc[base + (size_t)(t + 8) * 64 + dd] =
                    make_float2(to_tf32(c2 + cbv.x), to_tf32(c3 + cbv.y));
                *(float2*)&qr[base + (size_t)t * 64 + dd] =
                    make_float2(to_tf32(c0 + rbv.x), to_tf32(c1 + rbv.y));
                *(float2*)&qr[base + (size_t)(t + 8) * 64 + dd] =
                    make_float2(to_tf32(c2 + rbv.x), to_tf32(c3 + rbv.y));
            } else if (which == 1) {
                *(float2*)&kt[base + (size_t)t * 64 + dd] =
                    make_float2(to_tf32(c0), to_tf32(c1));
                *(float2*)&kt[base + (size_t)(t + 8) * 64 + dd] =
                    make_float2(to_tf32(c2), to_tf32(c3));
            } else {
                vt[base + (size_t)dd * 1024 + t]           = to_tf32(c0);
                vt[base + (size_t)(dd + 1) * 1024 + t]     = to_tf32(c1);
                vt[base + (size_t)dd * 1024 + t + 8]       = to_tf32(c2);
                vt[base + (size_t)(dd + 1) * 1024 + t + 8] = to_tf32(c3);
            }
        }
    }
}

// ---------------- out-proj GEMM ----------------
__global__ void __launch_bounds__(128, 2)
gemm_proj_tf32(const float* __restrict__ A, const float* __restrict__ B,
               const float* __restrict__ bias, float* __restrict__ C) {
    __shared__ float As[2][128 * ASTR];
    __shared__ float Bs[2][16 * BSTR];

    int tid = threadIdx.x;
    int wid = tid >> 5, lane = tid & 31;
    int lr = lane >> 2, lq = lane & 3;
    int wm = wid & 1, wn = wid >> 1;
    int n0 = blockIdx.x * 128, m0 = blockIdx.y * 128;

    int am[4], ak[4], bk[4], bn[4];
    #pragma unroll
    for (int l = 0; l < 4; l++) {
        int fidx = tid + 128 * l;
        am[l] = fidx >> 2;  ak[l] = (fidx & 3) << 2;
        bk[l] = fidx >> 5;  bn[l] = (fidx & 31) << 2;
    }

    float acc[4][8][4];
    #pragma unroll
    for (int mt = 0; mt < 4; mt++)
        #pragma unroll
        for (int nt = 0; nt < 8; nt++)
            #pragma unroll
            for (int r = 0; r < 4; r++) acc[mt][nt][r] = 0.0f;

    float4 pa[4], pb[4];
    #pragma unroll
    for (int l = 0; l < 4; l++) {
        pa[l] = *(const float4*)(A + (size_t)(m0 + am[l]) * HID + ak[l]);
        pb[l] = *(const float4*)(B + (size_t)bk[l] * EMB + n0 + bn[l]);
    }
    #pragma unroll
    for (int l = 0; l < 4; l++) {
        sts4_tf32(&As[0][am[l] * ASTR + ak[l]], pa[l]);
        sts4_tf32(&Bs[0][bk[l] * BSTR + bn[l]], pb[l]);
    }
    __syncthreads();

    for (int ks = 0; ks < 64; ks++) {
        int cur = ks & 1;
        if (ks < 63) {
            int k0 = (ks + 1) * 16;
            #pragma unroll
            for (int l = 0; l < 4; l++) {
                pa[l] = *(const float4*)(A + (size_t)(m0 + am[l]) * HID + k0 + ak[l]);
                pb[l] = *(const float4*)(B + (size_t)(k0 + bk[l]) * EMB + n0 + bn[l]);
            }
        }
        #pragma unroll
        for (int k8 = 0; k8 < 2; k8++) {
            int kb = k8 * 8 + 2 * lq;
            float2 av[4][2];
            #pragma unroll
            for (int mt = 0; mt < 4; mt++) {
                int r = wm * 64 + mt * 16 + lr;
                av[mt][0] = *(const float2*)&As[cur][r * ASTR + kb];
                av[mt][1] = *(const float2*)&As[cur][(r + 8) * ASTR + kb];
            }
            #pragma unroll
            for (int nt = 0; nt < 8; nt++) {
                int cc = wn * 64 + nt * 8 + lr;
                float bx = Bs[cur][kb * BSTR + cc];
                float by = Bs[cur][(kb + 1) * BSTR + cc];
                #pragma unroll
                for (int mt = 0; mt < 4; mt++)
                    mma8(acc[mt][nt], av[mt][0], av[mt][1], bx, by);
            }
        }
        if (ks < 63) {
            #pragma unroll
            for (int l = 0; l < 4; l++) {
                sts4_tf32(&As[cur ^ 1][am[l] * ASTR + ak[l]], pa[l]);
                sts4_tf32(&Bs[cur ^ 1][bk[l] * BSTR + bn[l]], pb[l]);
            }
        }
        __syncthreads();
    }

    #pragma unroll
    for (int mt = 0; mt < 4; mt++) {
        #pragma unroll
        for (int nt = 0; nt < 8; nt++) {
            int row = m0 + wm * 64 + mt * 16 + lr;
            int col = n0 + wn * 64 + nt * 8 + 2 * lq;
            float2 bb = *(const float2*)&bias[col];
            *(float2*)&C[(size_t)row * EMB + col] =
                make_float2(acc[mt][nt][0] + bb.x, acc[mt][nt][1] + bb.y);
            *(float2*)&C[(size_t)(row + 8) * EMB + col] =
                make_float2(acc[mt][nt][2] + bb.x, acc[mt][nt][3] + bb.y);
        }
    }
}

// ---------------- windowed attention (unchanged from R8) ----------------
#define TQ    64
#define SPAN  320
#define SP    328
#define AQP   68
#define RWP   68
#define PPW   272
#define KVP   68
#define KVSZ  4352
#define OFF_QC 0
#define OFF_QR 4352
#define OFF_RW 8704
#define OFF_SS 4352
#define OFF_PS 27200
#define OFF_KV 44608
#define ATTN_FLOATS 53312

__global__ void __launch_bounds__(256, 1)
attn_mma_kernel(const float* __restrict__ QC, const float* __restrict__ QR,
                const float* __restrict__ K,  const float* __restrict__ Vt,
                const float* __restrict__ RW, float* __restrict__ AO) {
    extern __shared__ float sm[];
    int tid = threadIdx.x;
    int wid = tid >> 5, lane = tid & 31;
    int lr = lane >> 2, lq = lane & 3;
    int wm = wid & 3, wn = wid >> 2;
    int t0 = blockIdx.x * TQ, h = blockIdx.y, b = blockIdx.z;
    size_t bh = (size_t)(b * HEADS + h);
    const float* qcb = QC + (bh << 16) + (size_t)t0 * 64;
    const float* qrb = QR + (bh << 16) + (size_t)t0 * 64;
    const float* kb  = K  + (bh << 16);
    const float* vb  = Vt + (bh << 16);
    int j0base = t0 - WIN;

    #pragma unroll
    for (int l = 0; l < 4; l++) {
        int fidx = tid + 256 * l;
        int t = fidx >> 4, d = (fidx & 15) << 2;
        *(float4*)&sm[OFF_QC + t * AQP + d] = *(const float4*)(qcb + t * 64 + d);
        *(float4*)&sm[OFF_QR + t * AQP + d] = *(const float4*)(qrb + t * 64 + d);
    }
    #pragma unroll 4
    for (int l = 0; l < 17; l++) {
        int fidx = tid + 256 * l;
        int u = fidx >> 4, d = (fidx & 15) << 2;
        *(float4*)&sm[OFF_RW + u * RWP + d] = *(const float4*)(RW + u * 64 + d);
    }
    __syncthreads();

    {
        float pc[17][4];
        #pragma unroll
        for (int nt = 0; nt < 17; nt++)
            #pragma unroll
            for (int r = 0; r < 4; r++) pc[nt][r] = 0.0f;
        #pragma unroll
        for (int k8 = 0; k8 < 8; k8++) {
            int kbi = k8 * 8 + 2 * lq;
            int r = wm * 16 + lr;
            float2 alo = *(const float2*)&sm[OFF_QR + r * AQP + kbi];
            float2 ahi = *(const float2*)&sm[OFF_QR + (r + 8) * AQP + kbi];
            #pragma unroll
            for (int nt = 0; nt < 17; nt++) {
                int cc = wn * 136 + nt * 8 + lr;
                float2 bv = *(const float2*)&sm[OFF_RW + cc * RWP + kbi];
                mma8(pc[nt], alo, ahi, bv.x, bv.y);
            }
        }
        #pragma unroll
        for (int nt = 0; nt < 17; nt++) {
            int cl = wn * 136 + nt * 8 + 2 * lq;
            int m = wm * 16 + lr;
            *(float2*)&sm[OFF_PS + m * PPW + cl]       = make_float2(pc[nt][0], pc[nt][1]);
            *(float2*)&sm[OFF_PS + (m + 8) * PPW + cl] = make_float2(pc[nt][2], pc[nt][3]);
        }
    }
    __syncthreads();

    {
        int j0 = j0base;
        if (j0 > -64) {
            #pragma unroll
            for (int l = 0; l < 4; l++) {
                int fidx = tid + 256 * l;
                int jl = fidx >> 4, d = (fidx & 15) << 2;
                int jg = j0 + jl;
                float4 v = make_float4(0.f, 0.f, 0.f, 0.f);
                if (jg >= 0 && jg < SEQ) v = *(const float4*)(kb + (size_t)jg * 64 + d);
                *(float4*)&sm[OFF_KV + jl * KVP + d] = v;
            }
        }
    }
    __syncthreads();

    for (int c = 0; c < 5; c++) {
        int cur = c & 1;
        int j0 = j0base + c * 64;
        bool live = (j0 > -64) && (j0 < SEQ);

        float4 pk[4];
        bool liven = false;
        if (c < 4) {
            int j0n = j0base + (c + 1) * 64;
            liven = (j0n > -64) && (j0n < SEQ);
            if (liven) {
                #pragma unroll
                for (int l = 0; l < 4; l++) {
                    int fidx = tid + 256 * l;
                    int jl = fidx >> 4, d = (fidx & 15) << 2;
                    int jg = j0n + jl;
                    pk[l] = make_float4(0.f, 0.f, 0.f, 0.f);
                    if (jg >= 0 && jg < SEQ) pk[l] = *(const float4*)(kb + (size_t)jg * 64 + d);
                }
            }
        }

        if (live) {
            float sc[4][4];
            #pragma unroll
            for (int nt = 0; nt < 4; nt++)
                #pragma unroll
                for (int r = 0; r < 4; r++) sc[nt][r] = 0.0f;
            #pragma unroll
            for (int k8 = 0; k8 < 8; k8++) {
                int kbi = k8 * 8 + 2 * lq;
                int r = wm * 16 + lr;
                float2 alo = *(const float2*)&sm[OFF_QC + r * AQP + kbi];
                float2 ahi = *(const float2*)&sm[OFF_QC + (r + 8) * AQP + kbi];
                #pragma unroll
                for (int nt = 0; nt < 4; nt++) {
                    int cc = wn * 32 + nt * 8 + lr;
                    float2 bv = *(const float2*)&sm[OFF_KV + cur * KVSZ + cc * KVP + kbi];
                    mma8(sc[nt], alo, ahi, bv.x, bv.y);
                }
            }
            #pragma unroll
            for (int nt = 0; nt < 4; nt++) {
                int cl = wn * 32 + nt * 8 + 2 * lq;
                #pragma unroll
                for (int e = 0; e < 4; e++) {
                    int m  = wm * 16 + lr + (e >> 1) * 8;
                    int jl = c * 64 + cl + (e & 1);
                    int jg = j0base + jl;
                    int u  = m - jl + 256;
                    float val = -1e30f;
                    if (jg >= 0 && jg < SEQ && u >= 0 && u < NREL)
                        val = (sc[nt][e] + sm[OFF_PS + m * PPW + u]) * SCALE;
                    sm[OFF_SS + m * SP + jl] = val;
                }
            }
        } else {
            #pragma unroll
            for (int nt = 0; nt < 4; nt++) {
                int cl = wn * 32 + nt * 8 + 2 * lq;
                #pragma unroll
                for (int e = 0; e < 4; e++) {
                    int m  = wm * 16 + lr + (e >> 1) * 8;
                    int jl = c * 64 + cl + (e & 1);
                    sm[OFF_SS + m * SP + jl] = -1e30f;
                }
            }
        }

        if (c < 4) {
            if (liven) {
                #pragma unroll
                for (int l = 0; l < 4; l++) {
                    int fidx = tid + 256 * l;
                    int jl = fidx >> 4, d = (fidx & 15) << 2;
                    *(float4*)&sm[OFF_KV + (cur ^ 1) * KVSZ + jl * KVP + d] = pk[l];
                }
            }
            __syncthreads();
        }
    }
    __syncthreads();

    {
        for (int t = wid * 8; t < wid * 8 + 8; t++) {
            float4* row = (float4*)&sm[OFF_SS + t * SP];
            float m = -1e30f;
            for (int i = lane; i < 80; i += 32) {
                float4 v = row[i];
                m = fmaxf(m, fmaxf(fmaxf(v.x, v.y), fmaxf(v.z, v.w)));
            }
            #pragma unroll
            for (int o = 16; o > 0; o >>= 1) m = fmaxf(m, __shfl_xor_sync(0xffffffffu, m, o));
            float s = 0.0f;
            for (int i = lane; i < 80; i += 32) {
                float4 v = row[i];
                v.x = __expf(v.x - m); v.y = __expf(v.y - m);
                v.z = __expf(v.z - m); v.w = __expf(v.w - m);
                s += v.x + v.y + v.z + v.w;
                row[i] = v;
            }
            #pragma unroll
            for (int o = 16; o > 0; o >>= 1) s += __shfl_xor_sync(0xffffffffu, s, o);
            float inv = 1.0f / s;
            for (int i = lane; i < 80; i += 32) {
                float4 v = row[i];
                v.x = to_tf32(v.x * inv); v.y = to_tf32(v.y * inv);
                v.z = to_tf32(v.z * inv); v.w = to_tf32(v.w * inv);
                row[i] = v;
            }
        }
    }
    __syncthreads();

    float ao_[4][4];
    #pragma unroll
    for (int nt = 0; nt < 4; nt++)
        #pragma unroll
        for (int r = 0; r < 4; r++) ao_[nt][r] = 0.0f;

    {
        int j0 = j0base;
        if (j0 > -64) {
            #pragma unroll
            for (int l = 0; l < 4; l++) {
                int fidx = tid + 256 * l;
                int dd = fidx >> 4, jl4 = (fidx & 15) << 2;
                int jg = j0 + jl4;
                float4 v;
                if (j0 >= 0 && j0 + 63 < SEQ) {
                    v = *(const float4*)(vb + (size_t)dd * 1024 + jg);
                } else {
                    v.x = (jg     >= 0 && jg     < SEQ) ? vb[(size_t)dd * 1024 + jg]     : 0.f;
                    v.y = (jg + 1 >= 0 && jg + 1 < SEQ) ? vb[(size_t)dd * 1024 + jg + 1] : 0.f;
                    v.z = (jg + 2 >= 0 && jg + 2 < SEQ) ? vb[(size_t)dd * 1024 + jg + 2] : 0.f;
                    v.w = (jg + 3 >= 0 && jg + 3 < SEQ) ? vb[(size_t)dd * 1024 + jg + 3] : 0.f;
                }
                *(float4*)&sm[OFF_KV + dd * KVP + jl4] = v;
            }
        }
    }
    __syncthreads();

    for (int c = 0; c < 5; c++) {
        int cur = c & 1;
        int j0 = j0base + c * 64;
        bool live = (j0 > -64) && (j0 < SEQ);

        float4 pk[4];
        bool liven = false;
        if (c < 4) {
            int j0n = j0base + (c + 1) * 64;
            liven = (j0n > -64) && (j0n < SEQ);
            if (liven) {
                #pragma unroll
                for (int l = 0; l < 4; l++) {
                    int fidx = tid + 256 * l;
                    int dd = fidx >> 4, jl4 = (fidx & 15) << 2;
                    int jg = j0n + jl4;
                    if (j0n >= 0 && j0n + 63 < SEQ) {
                        pk[l] = *(const float4*)(vb + (size_t)dd * 1024 + jg);
                    } else {
                        pk[l].x = (jg     >= 0 && jg     < SEQ) ? vb[(size_t)dd * 1024 + jg]     : 0.f;
                        pk[l].y = (jg + 1 >= 0 && jg + 1 < SEQ) ? vb[(size_t)dd * 1024 + jg + 1] : 0.f;
                        pk[l].z = (jg + 2 >= 0 && jg + 2 < SEQ) ? vb[(size_t)dd * 1024 + jg + 2] : 0.f;
                        pk[l].w = (jg + 3 >= 0 && jg + 3 < SEQ) ? vb[(size_t)dd * 1024 + jg + 3] : 0.f;
                    }
                }
            }
        }

        if (live) {
            #pragma unroll
            for (int k8 = 0; k8 < 8; k8++) {
                int kbi = k8 * 8 + 2 * lq;
                int r = wm * 16 + lr;
                float2 alo = *(const float2*)&sm[OFF_SS + r * SP + c * 64 + kbi];
                float2 ahi = *(const float2*)&sm[OFF_SS + (r + 8) * SP + c * 64 + kbi];
                #pragma unroll
                for (int nt = 0; nt < 4; nt++) {
                    int cc = wn * 32 + nt * 8 + lr;
                    float2 bv = *(const float2*)&sm[OFF_KV + cur * KVSZ + cc * KVP + kbi];
                    mma8(ao_[nt], alo, ahi, bv.x, bv.y);
                }
            }
        }

        if (c < 4) {
            if (liven) {
                #pragma unroll
                for (int l = 0; l < 4; l++) {
                    int fidx = tid + 256 * l;
                    int dd = fidx >> 4, jl4 = (fidx & 15) << 2;
                    *(float4*)&sm[OFF_KV + (cur ^ 1) * KVSZ + dd * KVP + jl4] = pk[l];
                }
            }
            __syncthreads();
        }
    }

    #pragma unroll
    for (int nt = 0; nt < 4; nt++) {
        int n = wn * 32 + nt * 8 + 2 * lq;
        int m = wm * 16 + lr;
        size_t o0 = ((size_t)(b * SEQ + t0 + m)) * HID + h * 64 + n;
        size_t o1 = ((size_t)(b * SEQ + t0 + m + 8)) * HID + h * 64 + n;
        *(float2*)&AO[o0] = make_float2(ao_[nt][0], ao_[nt][1]);
        *(float2*)&AO[o1] = make_float2(ao_[nt][2], ao_[nt][3]);
    }
}

// ---------------- host ----------------
extern "C" void kernel_launch(void* const* d_in, const int* in_sizes, int n_in,
                              void* d_out, int out_size) {
    const float* x    = (const float*)d_in[0];
    const float* Wq   = (const float*)d_in[1];
    const float* Wk   = (const float*)d_in[2];
    const float* Wv   = (const float*)d_in[3];
    const float* cb   = (const float*)d_in[4];
    const float* rb   = (const float*)d_in[5];
    const float* Wrel = (const float*)d_in[6];
    const float* brel = (const float*)d_in[7];
    const float* Wo   = (const float*)d_in[8];
    const float* bo   = (const float*)d_in[9];
    float* out = (float*)d_out;

    float *qc, *qr, *kt, *vt, *ao, *rwin;
    cudaGetSymbolAddress((void**)&qc,   g_qc);
    cudaGetSymbolAddress((void**)&qr,   g_qr);
    cudaGetSymbolAddress((void**)&kt,   g_k);
    cudaGetSymbolAddress((void**)&vt,   g_v);
    cudaGetSymbolAddress((void**)&ao,   g_ao);
    cudaGetSymbolAddress((void**)&rwin, g_rwin);

    rwin_kernel<<<(NRELP * 64 + 255) / 256, 256>>>(Wrel, brel, rwin);

    gemm_qkv_tf32<<<dim3(24, 32), 128>>>(x, Wq, Wk, Wv, cb, rb, qc, qr, kt, vt);

    size_t attn_smem = (size_t)ATTN_FLOATS * sizeof(float);
    cudaFuncSetAttribute(attn_mma_kernel, cudaFuncAttributeMaxDynamicSharedMemorySize,
                         (int)attn_smem);
    attn_mma_kernel<<<dim3(SEQ / TQ, HEADS, BATCH), 256, attn_smem>>>(
        qc, qr, kt, vt, rwin, ao);

    gemm_proj_tf32<<<dim3(8, 32), 128>>>(ao, Wo, bo, out);
}

// round 10
// speedup vs baseline: 2.7360x; 1.0523x over previous
#include <cuda_runtime.h>
#include <cuda_bf16.h>
#include <stdint.h>
#include <math.h>

#define BATCH 4
#define SEQ   1024
#define EMB   1024
#define HEADS 16
#define HDIM  64
#define HID   1024
#define WIN   128
#define NREL  257
#define NRELP 272
#define SCALE 0.03125f

// ---------------- scratch (all tf32-rounded at producer) ----------------
__device__ float g_qc[(size_t)BATCH*HEADS*SEQ*HDIM];   // [bh][t][d]
__device__ float g_qr[(size_t)BATCH*HEADS*SEQ*HDIM];   // [bh][t][d]
__device__ float g_k [(size_t)BATCH*HEADS*SEQ*HDIM];   // [bh][t][d]
__device__ float g_v [(size_t)BATCH*HEADS*SEQ*HDIM];   // [bh][d][t]  TRANSPOSED
__device__ float g_ao[(size_t)BATCH*SEQ*HID];          // fp32 [b][t][hid]
__device__ float g_rwin[NRELP*64];                     // [u][d], tf32

__device__ __forceinline__ float to_tf32(float x) {
    unsigned int r;
    asm("cvt.rna.tf32.f32 %0, %1;" : "=r"(r) : "f"(x));
    return __uint_as_float(r);
}

// ---------------- Rwin precompute ----------------
__global__ void rwin_kernel(const float* __restrict__ W_rel,
                            const float* __restrict__ b_rel,
                            float* __restrict__ Rwin) {
    int gid = blockIdx.x * blockDim.x + threadIdx.x;
    if (gid >= NRELP * 64) return;
    int d = gid & 63;
    int u = gid >> 6;
    float out = 0.0f;
    if (u < NREL) {
        float pos = (float)(u - WIN);
        float s = b_rel[d];
        #pragma unroll 8
        for (int f = 0; f < 32; f++) {
            float inv = powf(10000.0f, -(2.0f * (float)f) / 64.0f);
            float a = pos * inv;
            s += sinf(a) * W_rel[f * 64 + d];
            s += cosf(a) * W_rel[(f + 32) * 64 + d];
        }
        out = to_tf32(s);
    }
    Rwin[u * 64 + d] = out;
}

// ---------------- mma primitive ----------------
__device__ __forceinline__ void mma8(float c[4], float2 alo, float2 ahi, float b0, float b1) {
    asm volatile(
        "mma.sync.aligned.m16n8k8.row.col.f32.tf32.tf32.f32 "
        "{%0,%1,%2,%3}, {%4,%5,%6,%7}, {%8,%9}, {%0,%1,%2,%3};"
        : "+f"(c[0]), "+f"(c[1]), "+f"(c[2]), "+f"(c[3])
        : "r"(__float_as_uint(alo.x)), "r"(__float_as_uint(ahi.x)),
          "r"(__float_as_uint(alo.y)), "r"(__float_as_uint(ahi.y)),
          "r"(__float_as_uint(b0)),   "r"(__float_as_uint(b1)));
}

#define ASTR 18
#define BSTR 132

__device__ __forceinline__ void sts4_tf32(float* p, float4 v) {
    p[0] = to_tf32(v.x); p[1] = to_tf32(v.y);
    p[2] = to_tf32(v.z); p[3] = to_tf32(v.w);
}

// ---------------- fused QKV GEMM (unchanged from R9) ----------------
__global__ void __launch_bounds__(128, 2)
gemm_qkv_tf32(const float* __restrict__ X,
              const float* __restrict__ Wq, const float* __restrict__ Wk,
              const float* __restrict__ Wv,
              const float* __restrict__ cb, const float* __restrict__ rb,
              float* __restrict__ qc, float* __restrict__ qr,
              float* __restrict__ kt, float* __restrict__ vt) {
    __shared__ float As[2][128 * ASTR];
    __shared__ float Bs[2][16 * BSTR];

    int tid = threadIdx.x;
    int wid = tid >> 5, lane = tid & 31;
    int lr = lane >> 2, lq = lane & 3;
    int wm = wid & 1, wn = wid >> 1;
    int which = blockIdx.x >> 3;
    const float* B = (which == 0) ? Wq : ((which == 1) ? Wk : Wv);
    int n0 = (blockIdx.x & 7) * 128;
    int m0 = blockIdx.y * 128;

    int am[4], ak[4], bk[4], bn[4];
    #pragma unroll
    for (int l = 0; l < 4; l++) {
        int fidx = tid + 128 * l;
        am[l] = fidx >> 2;  ak[l] = (fidx & 3) << 2;
        bk[l] = fidx >> 5;  bn[l] = (fidx & 31) << 2;
    }

    float acc[4][8][4];
    #pragma unroll
    for (int mt = 0; mt < 4; mt++)
        #pragma unroll
        for (int nt = 0; nt < 8; nt++)
            #pragma unroll
            for (int r = 0; r < 4; r++) acc[mt][nt][r] = 0.0f;

    float4 pa[4], pb[4];
    #pragma unroll
    for (int l = 0; l < 4; l++) {
        pa[l] = *(const float4*)(X + (size_t)(m0 + am[l]) * EMB + ak[l]);
        pb[l] = *(const float4*)(B + (size_t)bk[l] * HID + n0 + bn[l]);
    }
    #pragma unroll
    for (int l = 0; l < 4; l++) {
        sts4_tf32(&As[0][am[l] * ASTR + ak[l]], pa[l]);
        sts4_tf32(&Bs[0][bk[l] * BSTR + bn[l]], pb[l]);
    }
    __syncthreads();

    for (int ks = 0; ks < 64; ks++) {
        int cur = ks & 1;
        if (ks < 63) {
            int k0 = (ks + 1) * 16;
            #pragma unroll
            for (int l = 0; l < 4; l++) {
                pa[l] = *(const float4*)(X + (size_t)(m0 + am[l]) * EMB + k0 + ak[l]);
                pb[l] = *(const float4*)(B + (size_t)(k0 + bk[l]) * HID + n0 + bn[l]);
            }
        }
        #pragma unroll
        for (int k8 = 0; k8 < 2; k8++) {
            int kb = k8 * 8 + 2 * lq;
            float2 av[4][2];
            #pragma unroll
            for (int mt = 0; mt < 4; mt++) {
                int r = wm * 64 + mt * 16 + lr;
                av[mt][0] = *(const float2*)&As[cur][r * ASTR + kb];
                av[mt][1] = *(const float2*)&As[cur][(r + 8) * ASTR + kb];
            }
            #pragma unroll
            for (int nt = 0; nt < 8; nt++) {
                int cc = wn * 64 + nt * 8 + lr;
                float bx = Bs[cur][kb * BSTR + cc];
                float by = Bs[cur][(kb + 1) * BSTR + cc];
                #pragma unroll
                for (int mt = 0; mt < 4; mt++)
                    mma8(acc[mt][nt], av[mt][0], av[mt][1], bx, by);
            }
        }
        if (ks < 63) {
            #pragma unroll
            for (int l = 0; l < 4; l++) {
                sts4_tf32(&As[cur ^ 1][am[l] * ASTR + ak[l]], pa[l]);
                sts4_tf32(&Bs[cur ^ 1][bk[l] * BSTR + bn[l]], pb[l]);
            }
        }
        __syncthreads();
    }

    #pragma unroll
    for (int mt = 0; mt < 4; mt++) {
        #pragma unroll
        for (int nt = 0; nt < 8; nt++) {
            int row = m0 + wm * 64 + mt * 16 + lr;
            int col = n0 + wn * 64 + nt * 8 + 2 * lq;
            float c0 = acc[mt][nt][0], c1 = acc[mt][nt][1];
            float c2 = acc[mt][nt][2], c3 = acc[mt][nt][3];
            int b = row >> 10, t = row & 1023;
            int hh = col >> 6, dd = col & 63;
            size_t base = (((size_t)(b * HEADS + hh)) << 16);
            if (which == 0) {
                float2 cbv = *(const float2*)&cb[col];
                float2 rbv = *(const float2*)&rb[col];
                *(float2*)&qc[base + (size_t)t * 64 + dd] =
                    make_float2(to_tf32(c0 + cbv.x), to_tf32(c1 + cbv.y));
                *(float2*)&qc[base + (size_t)(t + 8) * 64 + dd] =
                    make_float2(to_tf32(c2 + cbv.x), to_tf32(c3 + cbv.y));
                *(float2*)&qr[base + (size_t)t * 64 + dd] =
                    make_float2(to_tf32(c0 + rbv.x), to_tf32(c1 + rbv.y));
                *(float2*)&qr[base + (size_t)(t + 8) * 64 + dd] =
                    make_float2(to_tf32(c2 + rbv.x), to_tf32(c3 + rbv.y));
            } else if (which == 1) {
                *(float2*)&kt[base + (size_t)t * 64 + dd] =
                    make_float2(to_tf32(c0), to_tf32(c1));
                *(float2*)&kt[base + (size_t)(t + 8) * 64 + dd] =
                    make_float2(to_tf32(c2), to_tf32(c3));
            } else {
                vt[base + (size_t)dd * 1024 + t]           = to_tf32(c0);
                vt[base + (size_t)(dd + 1) * 1024 + t]     = to_tf32(c1);
                vt[base + (size_t)dd * 1024 + t + 8]       = to_tf32(c2);
                vt[base + (size_t)(dd + 1) * 1024 + t + 8] = to_tf32(c3);
            }
        }
    }
}

// ---------------- out-proj GEMM (unchanged from R9) ----------------
__global__ void __launch_bounds__(128, 2)
gemm_proj_tf32(const float* __restrict__ A, const float* __restrict__ B,
               const float* __restrict__ bias, float* __restrict__ C) {
    __shared__ float As[2][128 * ASTR];
    __shared__ float Bs[2][16 * BSTR];

    int tid = threadIdx.x;
    int wid = tid >> 5, lane = tid & 31;
    int lr = lane >> 2, lq = lane & 3;
    int wm = wid & 1, wn = wid >> 1;
    int n0 = blockIdx.x * 128, m0 = blockIdx.y * 128;

    int am[4], ak[4], bk[4], bn[4];
    #pragma unroll
    for (int l = 0; l < 4; l++) {
        int fidx = tid + 128 * l;
        am[l] = fidx >> 2;  ak[l] = (fidx & 3) << 2;
        bk[l] = fidx >> 5;  bn[l] = (fidx & 31) << 2;
    }

    float acc[4][8][4];
    #pragma unroll
    for (int mt = 0; mt < 4; mt++)
        #pragma unroll
        for (int nt = 0; nt < 8; nt++)
            #pragma unroll
            for (int r = 0; r < 4; r++) acc[mt][nt][r] = 0.0f;

    float4 pa[4], pb[4];
    #pragma unroll
    for (int l = 0; l < 4; l++) {
        pa[l] = *(const float4*)(A + (size_t)(m0 + am[l]) * HID + ak[l]);
        pb[l] = *(const float4*)(B + (size_t)bk[l] * EMB + n0 + bn[l]);
    }
    #pragma unroll
    for (int l = 0; l < 4; l++) {
        sts4_tf32(&As[0][am[l] * ASTR + ak[l]], pa[l]);
        sts4_tf32(&Bs[0][bk[l] * BSTR + bn[l]], pb[l]);
    }
    __syncthreads();

    for (int ks = 0; ks < 64; ks++) {
        int cur = ks & 1;
        if (ks < 63) {
            int k0 = (ks + 1) * 16;
            #pragma unroll
            for (int l = 0; l < 4; l++) {
                pa[l] = *(const float4*)(A + (size_t)(m0 + am[l]) * HID + k0 + ak[l]);
                pb[l] = *(const float4*)(B + (size_t)(k0 + bk[l]) * EMB + n0 + bn[l]);
            }
        }
        #pragma unroll
        for (int k8 = 0; k8 < 2; k8++) {
            int kb = k8 * 8 + 2 * lq;
            float2 av[4][2];
            #pragma unroll
            for (int mt = 0; mt < 4; mt++) {
                int r = wm * 64 + mt * 16 + lr;
                av[mt][0] = *(const float2*)&As[cur][r * ASTR + kb];
                av[mt][1] = *(const float2*)&As[cur][(r + 8) * ASTR + kb];
            }
            #pragma unroll
            for (int nt = 0; nt < 8; nt++) {
                int cc = wn * 64 + nt * 8 + lr;
                float bx = Bs[cur][kb * BSTR + cc];
                float by = Bs[cur][(kb + 1) * BSTR + cc];
                #pragma unroll
                for (int mt = 0; mt < 4; mt++)
                    mma8(acc[mt][nt], av[mt][0], av[mt][1], bx, by);
            }
        }
        if (ks < 63) {
            #pragma unroll
            for (int l = 0; l < 4; l++) {
                sts4_tf32(&As[cur ^ 1][am[l] * ASTR + ak[l]], pa[l]);
                sts4_tf32(&Bs[cur ^ 1][bk[l] * BSTR + bn[l]], pb[l]);
            }
        }
        __syncthreads();
    }

    #pragma unroll
    for (int mt = 0; mt < 4; mt++) {
        #pragma unroll
        for (int nt = 0; nt < 8; nt++) {
            int row = m0 + wm * 64 + mt * 16 + lr;
            int col = n0 + wn * 64 + nt * 8 + 2 * lq;
            float2 bb = *(const float2*)&bias[col];
            *(float2*)&C[(size_t)row * EMB + col] =
                make_float2(acc[mt][nt][0] + bb.x, acc[mt][nt][1] + bb.y);
            *(float2*)&C[(size_t)(row + 8) * EMB + col] =
                make_float2(acc[mt][nt][2] + bb.x, acc[mt][nt][3] + bb.y);
        }
    }
}

// ---------------- windowed attention: S in registers, 4 warps ----------------
// warp w owns rows [w*16, w*16+16). S acc = 40 n-tiles x 4 regs, in A-frag layout
// for the PV mma (C-frag of m16n8k8 == A-frag of next k8 mma). 2 CTAs/SM.
#define TQ    64
#define AQP   68    // Qc/Qr [t][d]
#define RWP   68    // Rwin [u][d]
#define PPW   272   // Prel [m][u]
#define KVP   68    // K [j][d] / V [d][j], single buffer
#define OFF_QC 0
#define OFF_QR 4352
#define OFF_RW 8704                 // 272*68 = 18496, end 27200
#define OFF_PS 4352                 // overlay on QR+RW: 64*272 = 17408, end 21760
#define OFF_KV 21760                // 64*68 = 4352, end 26112
#define ATTN_FLOATS 27200           // 108800 bytes

__global__ void __launch_bounds__(128, 2)
attn_mma_kernel(const float* __restrict__ QC, const float* __restrict__ QR,
                const float* __restrict__ K,  const float* __restrict__ Vt,
                const float* __restrict__ RW, float* __restrict__ AO) {
    extern __shared__ float sm[];
    int tid = threadIdx.x;
    int wid = tid >> 5, lane = tid & 31;
    int lr = lane >> 2, lq = lane & 3;
    int wm = wid;                       // warp owns rows [wm*16, wm*16+16)
    int t0 = blockIdx.x * TQ, h = blockIdx.y, b = blockIdx.z;
    size_t bh = (size_t)(b * HEADS + h);
    const float* qcb = QC + (bh << 16) + (size_t)t0 * 64;
    const float* qrb = QR + (bh << 16) + (size_t)t0 * 64;
    const float* kb  = K  + (bh << 16);
    const float* vb  = Vt + (bh << 16);
    int j0base = t0 - WIN;
    int r = wm * 16 + lr;

    // ---- load Qc, Qr ([t][d], pre-rounded tf32) ----
    #pragma unroll
    for (int l = 0; l < 8; l++) {
        int fidx = tid + 128 * l;
        int t = fidx >> 4, d = (fidx & 15) << 2;
        *(float4*)&sm[OFF_QC + t * AQP + d] = *(const float4*)(qcb + t * 64 + d);
        *(float4*)&sm[OFF_QR + t * AQP + d] = *(const float4*)(qrb + t * 64 + d);
    }
    // ---- load Rwin [u][d] ----
    #pragma unroll 4
    for (int l = 0; l < 34; l++) {
        int fidx = tid + 128 * l;
        int u = fidx >> 4, d = (fidx & 15) << 2;
        *(float4*)&sm[OFF_RW + u * RWP + d] = *(const float4*)(RW + u * 64 + d);
    }
    __syncthreads();

    // ---- Prel = Qr @ Rwin^T : each warp m16 x 272 ----
    {
        float pc[34][4];
        #pragma unroll
        for (int nt = 0; nt < 34; nt++)
            #pragma unroll
            for (int e = 0; e < 4; e++) pc[nt][e] = 0.0f;
        #pragma unroll
        for (int k8 = 0; k8 < 8; k8++) {
            int kbi = k8 * 8 + 2 * lq;
            float2 alo = *(const float2*)&sm[OFF_QR + r * AQP + kbi];
            float2 ahi = *(const float2*)&sm[OFF_QR + (r + 8) * AQP + kbi];
            #pragma unroll
            for (int nt = 0; nt < 34; nt++) {
                int cc = nt * 8 + lr;
                float2 bv = *(const float2*)&sm[OFF_RW + cc * RWP + kbi];
                mma8(pc[nt], alo, ahi, bv.x, bv.y);
            }
        }
        __syncthreads();   // all QR/RW reads complete before PS overlay write
        int m = wm * 16 + lr;
        #pragma unroll
        for (int nt = 0; nt < 34; nt++) {
            int cl = nt * 8 + 2 * lq;
            *(float2*)&sm[OFF_PS + m * PPW + cl]       = make_float2(pc[nt][0], pc[nt][1]);
            *(float2*)&sm[OFF_PS + (m + 8) * PPW + cl] = make_float2(pc[nt][2], pc[nt][3]);
        }
    }

    // ---- S = Qc @ K^T + gather(Prel), built in registers ----
    float sc[40][4];
    #pragma unroll
    for (int c = 0; c < 5; c++) {
        int j0 = j0base + c * 64;
        bool live = (j0 > -64) && (j0 < SEQ);
        __syncthreads();   // PS write / previous chunk K reads complete
        if (live) {
            #pragma unroll
            for (int l = 0; l < 8; l++) {
                int fidx = tid + 128 * l;
                int jl = fidx >> 4, d = (fidx & 15) << 2;
                int jg = j0 + jl;
                float4 v = make_float4(0.f, 0.f, 0.f, 0.f);
                if (jg >= 0 && jg < SEQ) v = *(const float4*)(kb + (size_t)jg * 64 + d);
                *(float4*)&sm[OFF_KV + jl * KVP + d] = v;
            }
        }
        __syncthreads();

        if (live) {
            #pragma unroll
            for (int nt = 0; nt < 8; nt++)
                #pragma unroll
                for (int e = 0; e < 4; e++) sc[c * 8 + nt][e] = 0.0f;
            #pragma unroll
            for (int k8 = 0; k8 < 8; k8++) {
                int kbi = k8 * 8 + 2 * lq;
                float2 alo = *(const float2*)&sm[OFF_QC + r * AQP + kbi];
                float2 ahi = *(const float2*)&sm[OFF_QC + (r + 8) * AQP + kbi];
                #pragma unroll
                for (int nt = 0; nt < 8; nt++) {
                    int cc = nt * 8 + lr;
                    float2 bv = *(const float2*)&sm[OFF_KV + cc * KVP + kbi];
                    mma8(sc[c * 8 + nt], alo, ahi, bv.x, bv.y);
                }
            }
            // add Prel diagonal, scale, mask
            #pragma unroll
            for (int nt = 0; nt < 8; nt++) {
                int cl = nt * 8 + 2 * lq;
                #pragma unroll
                for (int e = 0; e < 4; e++) {
                    int m  = wm * 16 + lr + (e >> 1) * 8;
                    int jl = c * 64 + cl + (e & 1);
                    int jg = j0base + jl;
                    int u  = m - jl + 256;
                    float val = -1e30f;
                    if (jg >= 0 && jg < SEQ && u >= 0 && u < NREL)
                        val = (sc[c * 8 + nt][e] + sm[OFF_PS + m * PPW + u]) * SCALE;
                    sc[c * 8 + nt][e] = val;
                }
            }
        } else {
            #pragma unroll
            for (int nt = 0; nt < 8; nt++)
                #pragma unroll
                for (int e = 0; e < 4; e++) sc[c * 8 + nt][e] = -1e30f;
        }
    }

    // ---- softmax in registers (rows r and r+8 per lane, quad-reduce) ----
    {
        float mx0 = -1e30f, mx1 = -1e30f;
        #pragma unroll
        for (int nt = 0; nt < 40; nt++) {
            mx0 = fmaxf(mx0, fmaxf(sc[nt][0], sc[nt][1]));
            mx1 = fmaxf(mx1, fmaxf(sc[nt][2], sc[nt][3]));
        }
        #pragma unroll
        for (int o = 1; o < 4; o <<= 1) {
            mx0 = fmaxf(mx0, __shfl_xor_sync(0xffffffffu, mx0, o));
            mx1 = fmaxf(mx1, __shfl_xor_sync(0xffffffffu, mx1, o));
        }
        float s0 = 0.0f, s1 = 0.0f;
        #pragma unroll
        for (int nt = 0; nt < 40; nt++) {
            sc[nt][0] = __expf(sc[nt][0] - mx0);
            sc[nt][1] = __expf(sc[nt][1] - mx0);
            sc[nt][2] = __expf(sc[nt][2] - mx1);
            sc[nt][3] = __expf(sc[nt][3] - mx1);
            s0 += sc[nt][0] + sc[nt][1];
            s1 += sc[nt][2] + sc[nt][3];
        }
        #pragma unroll
        for (int o = 1; o < 4; o <<= 1) {
            s0 += __shfl_xor_sync(0xffffffffu, s0, o);
            s1 += __shfl_xor_sync(0xffffffffu, s1, o);
        }
        float i0 = 1.0f / s0, i1 = 1.0f / s1;
        #pragma unroll
        for (int nt = 0; nt < 40; nt++) {
            sc[nt][0] = to_tf32(sc[nt][0] * i0);
            sc[nt][1] = to_tf32(sc[nt][1] * i0);
            sc[nt][2] = to_tf32(sc[nt][2] * i1);
            sc[nt][3] = to_tf32(sc[nt][3] * i1);
        }
    }

    // ---- O = P @ V : S regs are the A-frags directly; V smem [d][j] ----
    float ao_[8][4];
    #pragma unroll
    for (int nt = 0; nt < 8; nt++)
        #pragma unroll
        for (int e = 0; e < 4; e++) ao_[nt][e] = 0.0f;

    #pragma unroll
    for (int c = 0; c < 5; c++) {
        int j0 = j0base + c * 64;
        bool live = (j0 > -64) && (j0 < SEQ);
        __syncthreads();   // previous chunk V reads / last K reads complete
        if (live) {
            #pragma unroll
            for (int l = 0; l < 8; l++) {
                int fidx = tid + 128 * l;
                int dd = fidx >> 4, jl4 = (fidx & 15) << 2;
                int jg = j0 + jl4;
                float4 v;
                if (j0 >= 0 && j0 + 63 < SEQ) {
                    v = *(const float4*)(vb + (size_t)dd * 1024 + jg);
                } else {
                    v.x = (jg     >= 0 && jg     < SEQ) ? vb[(size_t)dd * 1024 + jg]     : 0.f;
                    v.y = (jg + 1 >= 0 && jg + 1 < SEQ) ? vb[(size_t)dd * 1024 + jg + 1] : 0.f;
                    v.z = (jg + 2 >= 0 && jg + 2 < SEQ) ? vb[(size_t)dd * 1024 + jg + 2] : 0.f;
                    v.w = (jg + 3 >= 0 && jg + 3 < SEQ) ? vb[(size_t)dd * 1024 + jg + 3] : 0.f;
                }
                *(float4*)&sm[OFF_KV + dd * KVP + jl4] = v;
            }
        }
        __syncthreads();

        if (live) {
            #pragma unroll
            for (int kk = 0; kk < 8; kk++) {
                int kbi = kk * 8 + 2 * lq;
                float2 alo = make_float2(sc[c * 8 + kk][0], sc[c * 8 + kk][1]);
                float2 ahi = make_float2(sc[c * 8 + kk][2], sc[c * 8 + kk][3]);
                #pragma unroll
                for (int nt = 0; nt < 8; nt++) {
                    int cc = nt * 8 + lr;
                    float2 bv = *(const float2*)&sm[OFF_KV + cc * KVP + kbi];
                    mma8(ao_[nt], alo, ahi, bv.x, bv.y);
                }
            }
        }
    }

    // ---- write AO[b][t0+m][h*64+n] ----
    #pragma unroll
    for (int nt = 0; nt < 8; nt++) {
        int n = nt * 8 + 2 * lq;
        int m = wm * 16 + lr;
        size_t o0 = ((size_t)(b * SEQ + t0 + m)) * HID + h * 64 + n;
        size_t o1 = ((size_t)(b * SEQ + t0 + m + 8)) * HID + h * 64 + n;
        *(float2*)&AO[o0] = make_float2(ao_[nt][0], ao_[nt][1]);
        *(float2*)&AO[o1] = make_float2(ao_[nt][2], ao_[nt][3]);
    }
}

// ---------------- host ----------------
extern "C" void kernel_launch(void* const* d_in, const int* in_sizes, int n_in,
                              void* d_out, int out_size) {
    const float* x    = (const float*)d_in[0];
    const float* Wq   = (const float*)d_in[1];
    const float* Wk   = (const float*)d_in[2];
    const float* Wv   = (const float*)d_in[3];
    const float* cb   = (const float*)d_in[4];
    const float* rb   = (const float*)d_in[5];
    const float* Wrel = (const float*)d_in[6];
    const float* brel = (const float*)d_in[7];
    const float* Wo   = (const float*)d_in[8];
    const float* bo   = (const float*)d_in[9];
    float* out = (float*)d_out;

    float *qc, *qr, *kt, *vt, *ao, *rwin;
    cudaGetSymbolAddress((void**)&qc,   g_qc);
    cudaGetSymbolAddress((void**)&qr,   g_qr);
    cudaGetSymbolAddress((void**)&kt,   g_k);
    cudaGetSymbolAddress((void**)&vt,   g_v);
    cudaGetSymbolAddress((void**)&ao,   g_ao);
    cudaGetSymbolAddress((void**)&rwin, g_rwin);

    rwin_kernel<<<(NRELP * 64 + 255) / 256, 256>>>(Wrel, brel, rwin);

    gemm_qkv_tf32<<<dim3(24, 32), 128>>>(x, Wq, Wk, Wv, cb, rb, qc, qr, kt, vt);

    size_t attn_smem = (size_t)ATTN_FLOATS * sizeof(float);
    cudaFuncSetAttribute(attn_mma_kernel, cudaFuncAttributeMaxDynamicSharedMemorySize,
                         (int)attn_smem);
    attn_mma_kernel<<<dim3(SEQ / TQ, HEADS, BATCH), 128, attn_smem>>>(
        qc, qr, kt, vt, rwin, ao);

    gemm_proj_tf32<<<dim3(8, 32), 128>>>(ao, Wo, bo, out);
}